// round 1
// baseline (speedup 1.0000x reference)
#include <cuda_runtime.h>
#include <math.h>

#define B_    16
#define NTOK  4096
#define C_    256
#define T_    (B_*NTOK)     // 65536 tokens
#define HID   1024
#define HDS   8
#define DH    32

// ---------------- scratch (static device globals; no runtime alloc) ----------------
__device__ float g_xn  [(size_t)T_*C_];
__device__ float g_tmp [(size_t)T_*C_];
__device__ float g_xa  [(size_t)T_*C_];
__device__ float g_qkv [(size_t)T_*3*C_];
__device__ float g_ctx [(size_t)B_*HDS*DH*DH];
__device__ float g_x1  [(size_t)T_*C_];
__device__ float g_f1  [(size_t)T_*HID];
__device__ float g_f2  [(size_t)T_*HID];
__device__ float g_x2  [(size_t)T_*C_];
__device__ float g_pavg[(size_t)B_*32*C_];
__device__ float g_pmax[(size_t)B_*32*C_];
__device__ float g_avg [B_*C_];
__device__ float g_mx  [B_*C_];
__device__ float g_ca  [B_*C_];
__device__ float g_sme [T_];
__device__ float g_smx [T_];
__device__ float g_sa  [T_];

__device__ __forceinline__ float gelu_f(float x){
    return 0.5f*x*(1.0f+erff(x*0.7071067811865476f));
}
__device__ __forceinline__ float sigmoid_f(float x){
    return 1.0f/(1.0f+expf(-x));
}

// ---------------- LayerNorm: warp per token (C=256 -> 8 floats/lane) ----------------
__global__ void ln_kernel(const float* __restrict__ in, const float* __restrict__ g,
                          const float* __restrict__ bta, float* __restrict__ out){
    int w = threadIdx.x>>5, lane = threadIdx.x&31;
    int t = blockIdx.x*8 + w;
    const float* row = in + (size_t)t*C_;
    float v[8]; float s=0.f, s2=0.f;
    #pragma unroll
    for(int i=0;i<8;i++){ v[i]=row[lane+32*i]; s+=v[i]; s2+=v[i]*v[i]; }
    #pragma unroll
    for(int o=16;o>0;o>>=1){ s+=__shfl_xor_sync(0xffffffffu,s,o); s2+=__shfl_xor_sync(0xffffffffu,s2,o); }
    float mean = s*(1.f/C_);
    float var  = s2*(1.f/C_) - mean*mean;
    float rstd = rsqrtf(var+1e-5f);
    float* orow = out + (size_t)t*C_;
    #pragma unroll
    for(int i=0;i<8;i++){ int c=lane+32*i; orow[c] = (v[i]-mean)*rstd*g[c]+bta[c]; }
}

// xa = xn + gelu(LN(sr))
__global__ void adapter_kernel(const float* __restrict__ sr, const float* __restrict__ xn,
                               const float* __restrict__ g, const float* __restrict__ bta,
                               float* __restrict__ out){
    int w = threadIdx.x>>5, lane = threadIdx.x&31;
    int t = blockIdx.x*8 + w;
    const float* row = sr + (size_t)t*C_;
    float v[8]; float s=0.f, s2=0.f;
    #pragma unroll
    for(int i=0;i<8;i++){ v[i]=row[lane+32*i]; s+=v[i]; s2+=v[i]*v[i]; }
    #pragma unroll
    for(int o=16;o>0;o>>=1){ s+=__shfl_xor_sync(0xffffffffu,s,o); s2+=__shfl_xor_sync(0xffffffffu,s2,o); }
    float mean = s*(1.f/C_);
    float var  = s2*(1.f/C_) - mean*mean;
    float rstd = rsqrtf(var+1e-5f);
    const float* xr = xn + (size_t)t*C_;
    float* orow = out + (size_t)t*C_;
    #pragma unroll
    for(int i=0;i<8;i++){
        int c=lane+32*i;
        float nv = (v[i]-mean)*rstd*g[c]+bta[c];
        orow[c] = xr[c] + gelu_f(nv);
    }
}

// ---------------- depthwise 3x3 'SAME' on [B,N,C] viewed as [B,C,64,64] ----------------
__global__ void dwconv3_kernel(const float* __restrict__ in, const float* __restrict__ wt,
                               const float* __restrict__ bias, float* __restrict__ out,
                               int C, int applyGelu){
    long long idx = (long long)blockIdx.x*blockDim.x + threadIdx.x;
    int c = (int)(idx % C);
    int n = (int)((idx / C) % NTOK);
    int b = (int)(idx / ((long long)C*NTOK));
    int y = n>>6, x = n&63;
    float s = bias[c];
    const float* wc = wt + c*9;
    #pragma unroll
    for(int dy=-1;dy<=1;dy++){
        int yy=y+dy; if(yy<0||yy>=64) continue;
        #pragma unroll
        for(int dx=-1;dx<=1;dx++){
            int xx=x+dx; if(xx<0||xx>=64) continue;
            s += in[((size_t)b*NTOK + yy*64+xx)*C + c]*wc[(dy+1)*3+(dx+1)];
        }
    }
    if(applyGelu) s = gelu_f(s);
    out[((size_t)b*NTOK + n)*C + c] = s;
}

// ---------------- SGEMM: out = A @ W^T (+bias)(+add0)(+add1) ----------------
// A[M,K], W[N,K] row-major; 128x128x16 tile, 8x8 per thread, 256 threads.
__global__ __launch_bounds__(256) void gemm_kernel(
    const float* __restrict__ A, const float* __restrict__ W,
    const float* __restrict__ bias, const float* __restrict__ add0,
    const float* __restrict__ add1, float* __restrict__ out,
    int M, int N, int K){
    __shared__ float As[16][132];
    __shared__ float Ws[16][132];
    int tid = threadIdx.x;
    int bm = blockIdx.y*128, bn = blockIdx.x*128;
    int lr = tid>>1, lk = (tid&1)*8;
    int ty = tid>>4, tx = tid&15;
    float acc[8][8];
    #pragma unroll
    for(int i=0;i<8;i++)
        #pragma unroll
        for(int j=0;j<8;j++) acc[i][j]=0.f;

    for(int k0=0;k0<K;k0+=16){
        const float4* Ap = (const float4*)(A + (size_t)(bm+lr)*K + k0 + lk);
        float4 a0=Ap[0], a1=Ap[1];
        As[lk+0][lr]=a0.x; As[lk+1][lr]=a0.y; As[lk+2][lr]=a0.z; As[lk+3][lr]=a0.w;
        As[lk+4][lr]=a1.x; As[lk+5][lr]=a1.y; As[lk+6][lr]=a1.z; As[lk+7][lr]=a1.w;
        const float4* Wp = (const float4*)(W + (size_t)(bn+lr)*K + k0 + lk);
        float4 w0=Wp[0], w1=Wp[1];
        Ws[lk+0][lr]=w0.x; Ws[lk+1][lr]=w0.y; Ws[lk+2][lr]=w0.z; Ws[lk+3][lr]=w0.w;
        Ws[lk+4][lr]=w1.x; Ws[lk+5][lr]=w1.y; Ws[lk+6][lr]=w1.z; Ws[lk+7][lr]=w1.w;
        __syncthreads();
        #pragma unroll
        for(int kk=0;kk<16;kk++){
            float4 af0 = *(const float4*)&As[kk][ty*8];
            float4 af1 = *(const float4*)&As[kk][ty*8+4];
            float4 wf0 = *(const float4*)&Ws[kk][tx*8];
            float4 wf1 = *(const float4*)&Ws[kk][tx*8+4];
            float a[8]={af0.x,af0.y,af0.z,af0.w,af1.x,af1.y,af1.z,af1.w};
            float w[8]={wf0.x,wf0.y,wf0.z,wf0.w,wf1.x,wf1.y,wf1.z,wf1.w};
            #pragma unroll
            for(int i=0;i<8;i++)
                #pragma unroll
                for(int j=0;j<8;j++) acc[i][j] = fmaf(a[i], w[j], acc[i][j]);
        }
        __syncthreads();
    }
    #pragma unroll
    for(int i=0;i<8;i++){
        int m = bm + ty*8 + i;
        size_t ro = (size_t)m*N + bn + tx*8;
        #pragma unroll
        for(int j=0;j<8;j++){
            float v = acc[i][j];
            int n = bn + tx*8 + j;
            if(bias) v += bias[n];
            if(add0) v += add0[ro+j];
            if(add1) v += add1[ro+j];
            out[ro+j] = v;
        }
    }
}

// ---------------- q softmax over tokens (axis N), per (b, col<256) ----------------
__global__ void softmax_q_kernel(float* __restrict__ qkv){
    int b   = blockIdx.x>>8;
    int col = blockIdx.x&255;
    int tid = threadIdx.x;
    __shared__ float red[256];
    float v[16]; float mx=-1e30f;
    size_t base = (size_t)b*NTOK*768 + col;
    #pragma unroll
    for(int i=0;i<16;i++){ v[i]=qkv[base + (size_t)(tid+i*256)*768]; mx=fmaxf(mx,v[i]); }
    red[tid]=mx; __syncthreads();
    for(int s=128;s>0;s>>=1){ if(tid<s) red[tid]=fmaxf(red[tid],red[tid+s]); __syncthreads(); }
    mx = red[0]; __syncthreads();
    float sum=0.f;
    #pragma unroll
    for(int i=0;i<16;i++){ v[i]=expf(v[i]-mx); sum+=v[i]; }
    red[tid]=sum; __syncthreads();
    for(int s=128;s>0;s>>=1){ if(tid<s) red[tid]+=red[tid+s]; __syncthreads(); }
    float inv = 1.f/red[0];
    #pragma unroll
    for(int i=0;i<16;i++) qkv[base + (size_t)(tid+i*256)*768] = v[i]*inv;
}

// ---------------- k softmax over head dim (32 contiguous), warp per (token, head) ----------------
__global__ void softmax_k_kernel(float* __restrict__ qkv){
    int wp = threadIdx.x>>5, lane = threadIdx.x&31;
    int p = blockIdx.x*8 + wp;
    int t = p>>3, h = p&7;
    size_t idx = (size_t)t*768 + 256 + h*32 + lane;
    float v = qkv[idx];
    float mx = v;
    #pragma unroll
    for(int o=16;o>0;o>>=1) mx = fmaxf(mx, __shfl_xor_sync(0xffffffffu,mx,o));
    float e = expf(v-mx), s=e;
    #pragma unroll
    for(int o=16;o>0;o>>=1) s += __shfl_xor_sync(0xffffffffu,s,o);
    qkv[idx] = e/s;
}

// ---------------- ctx[b,h,d,e] = sum_n k[n,d]*v[n,e]  (block per (b,h)) ----------------
__global__ __launch_bounds__(256) void ctx_kernel(const float* __restrict__ qkv, float* __restrict__ ctx){
    int b = blockIdx.x>>3, h = blockIdx.x&7;
    __shared__ float ks[32][33], vs[32][33];
    int tid = threadIdx.x;
    int row = tid>>3, colq = (tid&7)*4;
    int j = tid&31, i0 = (tid>>5)*4;
    size_t offK = 256 + h*32;
    float acc[4]={0,0,0,0};
    for(int n0=0;n0<NTOK;n0+=32){
        size_t rbase = ((size_t)b*NTOK + n0 + row)*768;
        float4 kv = *(const float4*)(qkv + rbase + offK + colq);
        float4 vv = *(const float4*)(qkv + rbase + offK + 256 + colq);
        ks[row][colq+0]=kv.x; ks[row][colq+1]=kv.y; ks[row][colq+2]=kv.z; ks[row][colq+3]=kv.w;
        vs[row][colq+0]=vv.x; vs[row][colq+1]=vv.y; vs[row][colq+2]=vv.z; vs[row][colq+3]=vv.w;
        __syncthreads();
        #pragma unroll 8
        for(int nn=0;nn<32;nn++){
            float vj = vs[nn][j];
            acc[0] = fmaf(ks[nn][i0+0], vj, acc[0]);
            acc[1] = fmaf(ks[nn][i0+1], vj, acc[1]);
            acc[2] = fmaf(ks[nn][i0+2], vj, acc[2]);
            acc[3] = fmaf(ks[nn][i0+3], vj, acc[3]);
        }
        __syncthreads();
    }
    float* cb = ctx + (size_t)(b*8+h)*1024;
    #pragma unroll
    for(int r=0;r<4;r++) cb[(i0+r)*32 + j] = acc[r];
}

// ---------------- attn[t,c] = sum_e q[t,h,e]*ctx[b,h,e,dd]  (block per (b, 64-token group)) ----------------
__global__ __launch_bounds__(256) void attn_kernel(const float* __restrict__ qkv,
                                                   const float* __restrict__ ctx,
                                                   float* __restrict__ out){
    __shared__ float cs[8192];
    __shared__ float qs[256];
    int b = blockIdx.x>>6;
    int grp = blockIdx.x&63;
    int tid = threadIdx.x;
    #pragma unroll
    for(int i=0;i<32;i++) cs[tid + i*256] = ctx[(size_t)b*8192 + tid + i*256];
    __syncthreads();
    int h = tid>>5, dd = tid&31;
    const float* ch = cs + h*1024;
    for(int tk=0;tk<64;tk++){
        size_t t = (size_t)b*NTOK + grp*64 + tk;
        qs[tid] = qkv[t*768 + tid];
        __syncthreads();
        float s = 0.f;
        #pragma unroll
        for(int e=0;e<32;e++) s = fmaf(qs[h*32+e], ch[e*32+dd], s);
        out[t*256 + tid] = s;
        __syncthreads();
    }
}

// ---------------- CSDA ----------------
__global__ void ca_stats1(const float* __restrict__ x, float* __restrict__ pavg, float* __restrict__ pmax){
    int b = blockIdx.x>>5, ch = blockIdx.x&31;
    int c = threadIdx.x;
    float s=0.f, m=-1e30f;
    for(int i=0;i<128;i++){
        float v = x[((size_t)b*NTOK + ch*128+i)*C_ + c];
        s += v; m = fmaxf(m,v);
    }
    pavg[(b*32+ch)*C_+c]=s; pmax[(b*32+ch)*C_+c]=m;
}
__global__ void ca_stats2(const float* __restrict__ pavg, const float* __restrict__ pmax,
                          float* __restrict__ avg, float* __restrict__ mx){
    int b=blockIdx.x; int c=threadIdx.x;
    float s=0.f, m=-1e30f;
    for(int i=0;i<32;i++){ s+=pavg[(b*32+i)*C_+c]; m=fmaxf(m,pmax[(b*32+i)*C_+c]); }
    avg[b*C_+c]=s*(1.f/4096.f); mx[b*C_+c]=m;
}
__global__ void ca_mlp_kernel(const float* __restrict__ avg, const float* __restrict__ mx,
                              const float* __restrict__ w1, const float* __restrict__ w2,
                              float* __restrict__ ca){
    int b = blockIdx.x;
    __shared__ float ha[16], hm[16];
    int tid = threadIdx.x;
    if(tid<16){
        float sa_=0.f, sm_=0.f;
        const float* w1r = w1 + tid*C_;
        for(int c=0;c<C_;c++){ sa_ += avg[b*C_+c]*w1r[c]; sm_ += mx[b*C_+c]*w1r[c]; }
        ha[tid]=fmaxf(sa_,0.f); hm[tid]=fmaxf(sm_,0.f);
    }
    __syncthreads();
    float s=0.f;
    const float* w2r = w2 + tid*16;
    #pragma unroll
    for(int j=0;j<16;j++) s += (ha[j]+hm[j])*w2r[j];
    ca[b*C_+tid] = sigmoid_f(s);
}
__global__ void smap_kernel(const float* __restrict__ x2, const float* __restrict__ ca,
                            float* __restrict__ smean, float* __restrict__ smax){
    int w = threadIdx.x>>5, lane = threadIdx.x&31;
    int t = blockIdx.x*8 + w;
    int b = t>>12;
    const float* row = x2 + (size_t)t*C_;
    const float* cab = ca + b*C_;
    float s=0.f, m=-1e30f;
    #pragma unroll
    for(int i=0;i<8;i++){ int c=lane+32*i; float v=row[c]*cab[c]; s+=v; m=fmaxf(m,v); }
    #pragma unroll
    for(int o=16;o>0;o>>=1){ s+=__shfl_xor_sync(0xffffffffu,s,o); m=fmaxf(m,__shfl_xor_sync(0xffffffffu,m,o)); }
    if(lane==0){ smean[t]=s*(1.f/C_); smax[t]=m; }
}
__global__ void spconv_kernel(const float* __restrict__ smean, const float* __restrict__ smax,
                              const float* __restrict__ w, const float* __restrict__ bias,
                              float* __restrict__ sa){
    int t = blockIdx.x*256 + threadIdx.x;
    int b = t>>12, n = t&4095;
    int y = n>>6, x = n&63;
    float s = bias[0];
    for(int dy=-3;dy<=3;dy++){
        int yy=y+dy; if(yy<0||yy>=64) continue;
        for(int dx=-3;dx<=3;dx++){
            int xx=x+dx; if(xx<0||xx>=64) continue;
            int nn = b*4096 + yy*64+xx;
            int wi = (dy+3)*7+(dx+3);
            s += smean[nn]*w[wi] + smax[nn]*w[49+wi];
        }
    }
    sa[t] = sigmoid_f(s);
}
__global__ void final_kernel(const float* __restrict__ x2, const float* __restrict__ ca,
                             const float* __restrict__ sa, float* __restrict__ out){
    size_t i = (size_t)blockIdx.x*256 + threadIdx.x;
    int c = (int)(i & 255);
    int t = (int)(i >> 8);
    int b = t >> 12;
    out[i] = x2[i]*ca[b*256+c]*sa[t];
}

// ---------------- host ----------------
static inline void gemm(const float*A,const float*W,const float*bias,const float*a0,
                        const float*a1,float*out,int M,int N,int K){
    dim3 g(N/128, M/128);
    gemm_kernel<<<g,256>>>(A,W,bias,a0,a1,out,M,N,K);
}

extern "C" void kernel_launch(void* const* d_in, const int* in_sizes, int n_in,
                              void* d_out, int out_size){
    const float* x      = (const float*)d_in[0];
    const float* n1_g   = (const float*)d_in[3];
    const float* n1_b   = (const float*)d_in[4];
    const float* sr_w   = (const float*)d_in[5];
    const float* sr_b   = (const float*)d_in[6];
    const float* an_g   = (const float*)d_in[7];
    const float* an_b   = (const float*)d_in[8];
    const float* qkv_w  = (const float*)d_in[9];
    const float* proj_w = (const float*)d_in[10];
    const float* proj_b = (const float*)d_in[11];
    const float* n2_g   = (const float*)d_in[12];
    const float* n2_b   = (const float*)d_in[13];
    const float* fc1_w  = (const float*)d_in[14];
    const float* fc1_b  = (const float*)d_in[15];
    const float* dw_w   = (const float*)d_in[16];
    const float* dw_b   = (const float*)d_in[17];
    const float* fc2_w  = (const float*)d_in[18];
    const float* fc2_b  = (const float*)d_in[19];
    const float* ca_w1  = (const float*)d_in[20];
    const float* ca_w2  = (const float*)d_in[21];
    const float* sp_w   = (const float*)d_in[22];
    const float* sp_b   = (const float*)d_in[23];
    float* out = (float*)d_out;

    float *xn,*tmp,*xa,*qkv,*ctx,*x1,*f1,*f2,*x2,*pavg,*pmax,*avg,*mx,*ca,*sme,*smx,*sa;
    cudaGetSymbolAddress((void**)&xn,  g_xn);
    cudaGetSymbolAddress((void**)&tmp, g_tmp);
    cudaGetSymbolAddress((void**)&xa,  g_xa);
    cudaGetSymbolAddress((void**)&qkv, g_qkv);
    cudaGetSymbolAddress((void**)&ctx, g_ctx);
    cudaGetSymbolAddress((void**)&x1,  g_x1);
    cudaGetSymbolAddress((void**)&f1,  g_f1);
    cudaGetSymbolAddress((void**)&f2,  g_f2);
    cudaGetSymbolAddress((void**)&x2,  g_x2);
    cudaGetSymbolAddress((void**)&pavg,g_pavg);
    cudaGetSymbolAddress((void**)&pmax,g_pmax);
    cudaGetSymbolAddress((void**)&avg, g_avg);
    cudaGetSymbolAddress((void**)&mx,  g_mx);
    cudaGetSymbolAddress((void**)&ca,  g_ca);
    cudaGetSymbolAddress((void**)&sme, g_sme);
    cudaGetSymbolAddress((void**)&smx, g_smx);
    cudaGetSymbolAddress((void**)&sa,  g_sa);

    const int TB = T_/8;   // 8192 blocks for warp-per-token kernels

    // ---- attention branch ----
    ln_kernel<<<TB,256>>>(x, n1_g, n1_b, xn);
    dwconv3_kernel<<<(T_*C_)/256,256>>>(xn, sr_w, sr_b, tmp, C_, 0);
    adapter_kernel<<<TB,256>>>(tmp, xn, an_g, an_b, xa);
    gemm(xa, qkv_w, nullptr, nullptr, nullptr, qkv, T_, 3*C_, C_);
    softmax_q_kernel<<<B_*C_,256>>>(qkv);
    softmax_k_kernel<<<T_,256>>>(qkv);
    ctx_kernel<<<B_*HDS,256>>>(qkv, ctx);
    attn_kernel<<<B_*64,256>>>(qkv, ctx, tmp);
    gemm(tmp, proj_w, proj_b, x, xn, x1, T_, C_, C_);

    // ---- MixFFN ----
    ln_kernel<<<TB,256>>>(x1, n2_g, n2_b, xa);
    gemm(xa, fc1_w, fc1_b, nullptr, nullptr, f1, T_, HID, C_);
    dwconv3_kernel<<<((size_t)T_*HID)/256,256>>>(f1, dw_w, dw_b, f2, HID, 1);
    gemm(f2, fc2_w, fc2_b, x1, nullptr, x2, T_, C_, HID);

    // ---- CSDA ----
    ca_stats1<<<B_*32,256>>>(x2, pavg, pmax);
    ca_stats2<<<B_,256>>>(pavg, pmax, avg, mx);
    ca_mlp_kernel<<<B_,256>>>(avg, mx, ca_w1, ca_w2, ca);
    smap_kernel<<<TB,256>>>(x2, ca, sme, smx);
    spconv_kernel<<<T_/256,256>>>(sme, smx, sp_w, sp_b, sa);
    final_kernel<<<(T_*C_)/256,256>>>(x2, ca, sa, out);
}

// round 3
// speedup vs baseline: 1.4730x; 1.4730x over previous
#include <cuda_runtime.h>
#include <math.h>
#include <stdint.h>

#define B_    16
#define NTOK  4096
#define C_    256
#define T_    (B_*NTOK)     // 65536 tokens
#define HID   1024
#define HDS   8
#define DH    32

// ---------------- scratch ----------------
__device__ float g_xn  [(size_t)T_*C_];
__device__ float g_tmp [(size_t)T_*C_];
__device__ float g_xa  [(size_t)T_*C_];
__device__ float g_qkv [(size_t)T_*3*C_];
__device__ float g_ctx [(size_t)B_*HDS*DH*DH];
__device__ float g_x1  [(size_t)T_*C_];
__device__ float g_f1  [(size_t)T_*HID];
__device__ float g_f2  [(size_t)T_*HID];
__device__ float g_x2  [(size_t)T_*C_];
__device__ float g_qmx [B_*C_];
__device__ float g_qrs [B_*C_];
__device__ float g_pavg[(size_t)B_*32*C_];
__device__ float g_pmax[(size_t)B_*32*C_];
__device__ float g_avg [B_*C_];
__device__ float g_mx  [B_*C_];
__device__ float g_ca  [B_*C_];
__device__ float g_sme [T_];
__device__ float g_smx [T_];
__device__ float g_sa  [T_];

__device__ __forceinline__ float gelu_f(float x){
    return 0.5f*x*(1.0f+erff(x*0.7071067811865476f));
}
__device__ __forceinline__ float sigmoid_f(float x){
    return 1.0f/(1.0f+expf(-x));
}
__device__ __forceinline__ uint32_t f2tf(float f){
    uint32_t u; asm("cvt.rna.tf32.f32 %0, %1;" : "=r"(u) : "f"(f)); return u;
}
__device__ __forceinline__ void mma_tf32(float* c, const uint32_t* a, const uint32_t* b){
    asm volatile("mma.sync.aligned.m16n8k8.row.col.f32.tf32.tf32.f32 "
        "{%0,%1,%2,%3}, {%4,%5,%6,%7}, {%8,%9}, {%0,%1,%2,%3};\n"
        : "+f"(c[0]),"+f"(c[1]),"+f"(c[2]),"+f"(c[3])
        : "r"(a[0]),"r"(a[1]),"r"(a[2]),"r"(a[3]), "r"(b[0]),"r"(b[1]));
}

// ---------------- LayerNorm ----------------
__global__ void ln_kernel(const float* __restrict__ in, const float* __restrict__ g,
                          const float* __restrict__ bta, float* __restrict__ out){
    int w = threadIdx.x>>5, lane = threadIdx.x&31;
    int t = blockIdx.x*8 + w;
    const float* row = in + (size_t)t*C_;
    float v[8]; float s=0.f, s2=0.f;
    #pragma unroll
    for(int i=0;i<8;i++){ v[i]=row[lane+32*i]; s+=v[i]; s2+=v[i]*v[i]; }
    #pragma unroll
    for(int o=16;o>0;o>>=1){ s+=__shfl_xor_sync(0xffffffffu,s,o); s2+=__shfl_xor_sync(0xffffffffu,s2,o); }
    float mean = s*(1.f/C_);
    float var  = s2*(1.f/C_) - mean*mean;
    float rstd = rsqrtf(var+1e-5f);
    float* orow = out + (size_t)t*C_;
    #pragma unroll
    for(int i=0;i<8;i++){ int c=lane+32*i; orow[c] = (v[i]-mean)*rstd*g[c]+bta[c]; }
}

__global__ void adapter_kernel(const float* __restrict__ sr, const float* __restrict__ xn,
                               const float* __restrict__ g, const float* __restrict__ bta,
                               float* __restrict__ out){
    int w = threadIdx.x>>5, lane = threadIdx.x&31;
    int t = blockIdx.x*8 + w;
    const float* row = sr + (size_t)t*C_;
    float v[8]; float s=0.f, s2=0.f;
    #pragma unroll
    for(int i=0;i<8;i++){ v[i]=row[lane+32*i]; s+=v[i]; s2+=v[i]*v[i]; }
    #pragma unroll
    for(int o=16;o>0;o>>=1){ s+=__shfl_xor_sync(0xffffffffu,s,o); s2+=__shfl_xor_sync(0xffffffffu,s2,o); }
    float mean = s*(1.f/C_);
    float var  = s2*(1.f/C_) - mean*mean;
    float rstd = rsqrtf(var+1e-5f);
    const float* xr = xn + (size_t)t*C_;
    float* orow = out + (size_t)t*C_;
    #pragma unroll
    for(int i=0;i<8;i++){
        int c=lane+32*i;
        float nv = (v[i]-mean)*rstd*g[c]+bta[c];
        orow[c] = xr[c] + gelu_f(nv);
    }
}

// ---------------- depthwise 3x3, float4 over channels ----------------
__global__ void dwconv3_kernel4(const float* __restrict__ in, const float* __restrict__ wt,
                                const float* __restrict__ bias, float* __restrict__ out,
                                int C, int applyGelu){
    int idx = blockIdx.x*blockDim.x + threadIdx.x;
    int Cv = C>>2;
    int cg = idx % Cv;
    int n  = (idx / Cv) & 4095;
    int b  = idx / (Cv*4096);
    int c4 = cg*4;
    int y = n>>6, x = n&63;
    float4 s = *(const float4*)(bias + c4);
    float w[4][9];
    #pragma unroll
    for(int j=0;j<4;j++)
        #pragma unroll
        for(int t=0;t<9;t++) w[j][t] = wt[(c4+j)*9+t];
    #pragma unroll
    for(int dy=-1;dy<=1;dy++){
        int yy=y+dy; if((unsigned)yy>=64u) continue;
        #pragma unroll
        for(int dx=-1;dx<=1;dx++){
            int xx=x+dx; if((unsigned)xx>=64u) continue;
            float4 v = *(const float4*)(in + ((size_t)b*4096 + yy*64+xx)*C + c4);
            int t=(dy+1)*3+(dx+1);
            s.x += v.x*w[0][t]; s.y += v.y*w[1][t];
            s.z += v.z*w[2][t]; s.w += v.w*w[3][t];
        }
    }
    if(applyGelu){ s.x=gelu_f(s.x); s.y=gelu_f(s.y); s.z=gelu_f(s.z); s.w=gelu_f(s.w); }
    *(float4*)(out + ((size_t)b*4096 + n)*C + c4) = s;
}

// ---------------- TF32 tensor-core GEMM: out = A @ W^T (+bias)(+add0)(+add1) ----------------
// A[M,K], W[N,K] row-major. Tile 128x128x32. 8 warps (2M x 4N), warp tile 64x32.
__global__ __launch_bounds__(256,1) void gemm_tf32_kernel(
    const float* __restrict__ A, const float* __restrict__ W,
    const float* __restrict__ bias, const float* __restrict__ add0,
    const float* __restrict__ add1, float* __restrict__ out,
    int M, int N, int K){
    __shared__ uint32_t As[32*136];
    __shared__ uint32_t Ws[32*136];
    int tid = threadIdx.x;
    int bm = blockIdx.y*128, bn = blockIdx.x*128;
    int wid = tid>>5, lane = tid&31;
    int wm = wid&1, wn = wid>>1;
    int g = lane>>2, tg = lane&3;
    float acc[4][4][4];
    #pragma unroll
    for(int mi=0;mi<4;mi++)
        #pragma unroll
        for(int ni=0;ni<4;ni++)
            #pragma unroll
            for(int r=0;r<4;r++) acc[mi][ni][r]=0.f;

    int lm = tid>>1, lk = (tid&1)*16;
    const float* Ap = A + (size_t)(bm+lm)*K + lk;
    const float* Wp = W + (size_t)(bn+lm)*K + lk;

    for(int k0=0;k0<K;k0+=32){
        #pragma unroll
        for(int j=0;j<4;j++){
            float4 av = *(const float4*)(Ap + k0 + j*4);
            float4 wv = *(const float4*)(Wp + k0 + j*4);
            int kr = lk + j*4;
            As[(kr+0)*136+lm]=f2tf(av.x); As[(kr+1)*136+lm]=f2tf(av.y);
            As[(kr+2)*136+lm]=f2tf(av.z); As[(kr+3)*136+lm]=f2tf(av.w);
            Ws[(kr+0)*136+lm]=f2tf(wv.x); Ws[(kr+1)*136+lm]=f2tf(wv.y);
            Ws[(kr+2)*136+lm]=f2tf(wv.z); Ws[(kr+3)*136+lm]=f2tf(wv.w);
        }
        __syncthreads();
        #pragma unroll
        for(int k8=0;k8<32;k8+=8){
            uint32_t af[4][4], bf[4][2];
            #pragma unroll
            for(int mi=0;mi<4;mi++){
                int row = wm*64 + mi*16 + g;
                af[mi][0]=As[(k8+tg)*136+row];
                af[mi][1]=As[(k8+tg)*136+row+8];
                af[mi][2]=As[(k8+tg+4)*136+row];
                af[mi][3]=As[(k8+tg+4)*136+row+8];
            }
            #pragma unroll
            for(int ni=0;ni<4;ni++){
                int col = wn*32 + ni*8 + g;
                bf[ni][0]=Ws[(k8+tg)*136+col];
                bf[ni][1]=Ws[(k8+tg+4)*136+col];
            }
            #pragma unroll
            for(int mi=0;mi<4;mi++)
                #pragma unroll
                for(int ni=0;ni<4;ni++)
                    mma_tf32(acc[mi][ni], af[mi], bf[ni]);
        }
        __syncthreads();
    }
    // epilogue: c0:(g, tg*2) c1:(g, tg*2+1) c2:(g+8, tg*2) c3:(g+8, tg*2+1)
    #pragma unroll
    for(int mi=0;mi<4;mi++){
        int row0 = bm + wm*64 + mi*16 + g;
        #pragma unroll
        for(int ni=0;ni<4;ni++){
            int col = bn + wn*32 + ni*8 + tg*2;
            size_t o0 = (size_t)row0*N + col;
            size_t o1 = (size_t)(row0+8)*N + col;
            float v0=acc[mi][ni][0], v1=acc[mi][ni][1], v2=acc[mi][ni][2], v3=acc[mi][ni][3];
            if(bias){ float b0=bias[col], b1=bias[col+1]; v0+=b0; v1+=b1; v2+=b0; v3+=b1; }
            if(add0){ v0+=add0[o0]; v1+=add0[o0+1]; v2+=add0[o1]; v3+=add0[o1+1]; }
            if(add1){ v0+=add1[o0]; v1+=add1[o0+1]; v2+=add1[o1]; v3+=add1[o1+1]; }
            out[o0]=v0; out[o0+1]=v1; out[o1]=v2; out[o1+1]=v3;
        }
    }
}

// ---------------- q column stats: max & 1/sumexp over tokens per (b,col) ----------------
__global__ void qcolstats_kernel(const float* __restrict__ qkv,
                                 float* __restrict__ qmx, float* __restrict__ qrs){
    int b   = blockIdx.x>>8;
    int col = blockIdx.x&255;
    int tid = threadIdx.x;
    __shared__ float red[256];
    float v[16]; float mx=-1e30f;
    size_t base = (size_t)b*NTOK*768 + col;
    #pragma unroll
    for(int i=0;i<16;i++){ v[i]=qkv[base + (size_t)(tid+i*256)*768]; mx=fmaxf(mx,v[i]); }
    red[tid]=mx; __syncthreads();
    for(int s=128;s>0;s>>=1){ if(tid<s) red[tid]=fmaxf(red[tid],red[tid+s]); __syncthreads(); }
    mx = red[0]; __syncthreads();
    float sum=0.f;
    #pragma unroll
    for(int i=0;i<16;i++) sum += expf(v[i]-mx);
    red[tid]=sum; __syncthreads();
    for(int s=128;s>0;s>>=1){ if(tid<s) red[tid]+=red[tid+s]; __syncthreads(); }
    if(tid==0){ qmx[b*C_+col]=mx; qrs[b*C_+col]=1.f/red[0]; }
}

// ---------------- k softmax over head dim ----------------
__global__ void softmax_k_kernel(float* __restrict__ qkv){
    int wp = threadIdx.x>>5, lane = threadIdx.x&31;
    int p = blockIdx.x*8 + wp;
    int t = p>>3, h = p&7;
    size_t idx = (size_t)t*768 + 256 + h*32 + lane;
    float v = qkv[idx];
    float mx = v;
    #pragma unroll
    for(int o=16;o>0;o>>=1) mx = fmaxf(mx, __shfl_xor_sync(0xffffffffu,mx,o));
    float e = expf(v-mx), s=e;
    #pragma unroll
    for(int o=16;o>0;o>>=1) s += __shfl_xor_sync(0xffffffffu,s,o);
    qkv[idx] = e/s;
}

// ---------------- ctx[b,h,d,e] = sum_n k[n,d]*v[n,e] ----------------
__global__ __launch_bounds__(256) void ctx_kernel(const float* __restrict__ qkv, float* __restrict__ ctx){
    int b = blockIdx.x>>3, h = blockIdx.x&7;
    __shared__ float ks[32][33], vs[32][33];
    int tid = threadIdx.x;
    int row = tid>>3, colq = (tid&7)*4;
    int j = tid&31, i0 = (tid>>5)*4;
    size_t offK = 256 + h*32;
    float acc[4]={0,0,0,0};
    for(int n0=0;n0<NTOK;n0+=32){
        size_t rbase = ((size_t)b*NTOK + n0 + row)*768;
        float4 kv = *(const float4*)(qkv + rbase + offK + colq);
        float4 vv = *(const float4*)(qkv + rbase + offK + 256 + colq);
        ks[row][colq+0]=kv.x; ks[row][colq+1]=kv.y; ks[row][colq+2]=kv.z; ks[row][colq+3]=kv.w;
        vs[row][colq+0]=vv.x; vs[row][colq+1]=vv.y; vs[row][colq+2]=vv.z; vs[row][colq+3]=vv.w;
        __syncthreads();
        #pragma unroll 8
        for(int nn=0;nn<32;nn++){
            float vj = vs[nn][j];
            acc[0] = fmaf(ks[nn][i0+0], vj, acc[0]);
            acc[1] = fmaf(ks[nn][i0+1], vj, acc[1]);
            acc[2] = fmaf(ks[nn][i0+2], vj, acc[2]);
            acc[3] = fmaf(ks[nn][i0+3], vj, acc[3]);
        }
        __syncthreads();
    }
    float* cb = ctx + (size_t)(b*8+h)*1024;
    #pragma unroll
    for(int r=0;r<4;r++) cb[(i0+r)*32 + j] = acc[r];
}

// ---------------- fused q-softmax + attn: out[t,c] = sum_e softmax_q[t,h,e]*ctx[b,h,e,c%32] ----
__global__ __launch_bounds__(256) void attn_kernel2(const float* __restrict__ qkv,
                                                    const float* __restrict__ ctx,
                                                    const float* __restrict__ qmx,
                                                    const float* __restrict__ qrs,
                                                    float* __restrict__ out){
    __shared__ float cs[8192];
    __shared__ float qs[8][256];
    int b = blockIdx.x>>6;
    int grp = blockIdx.x&63;
    int tid = threadIdx.x;
    #pragma unroll
    for(int i=0;i<32;i++) cs[tid + i*256] = ctx[(size_t)b*8192 + tid + i*256];
    float cmx = qmx[b*C_+tid];
    float crs = qrs[b*C_+tid];
    int h = tid>>5, dd = tid&31;
    const float* ch = cs + h*1024;
    __syncthreads();
    for(int t8=0;t8<8;t8++){
        size_t t0 = (size_t)b*NTOK + grp*64 + t8*8;
        #pragma unroll
        for(int i=0;i<8;i++)
            qs[i][tid] = expf(qkv[(t0+i)*768 + tid] - cmx)*crs;
        __syncthreads();
        #pragma unroll
        for(int i=0;i<8;i++){
            float s = 0.f;
            #pragma unroll
            for(int e=0;e<32;e++) s = fmaf(qs[i][h*32+e], ch[e*32+dd], s);
            out[(t0+i)*256 + tid] = s;
        }
        __syncthreads();
    }
}

// ---------------- CSDA ----------------
__global__ void ca_stats1(const float* __restrict__ x, float* __restrict__ pavg, float* __restrict__ pmax){
    int b = blockIdx.x>>5, ch = blockIdx.x&31;
    int c = threadIdx.x;
    float s=0.f, m=-1e30f;
    for(int i=0;i<128;i++){
        float v = x[((size_t)b*NTOK + ch*128+i)*C_ + c];
        s += v; m = fmaxf(m,v);
    }
    pavg[(b*32+ch)*C_+c]=s; pmax[(b*32+ch)*C_+c]=m;
}
__global__ void ca_stats2(const float* __restrict__ pavg, const float* __restrict__ pmax,
                          float* __restrict__ avg, float* __restrict__ mx){
    int b=blockIdx.x; int c=threadIdx.x;
    float s=0.f, m=-1e30f;
    for(int i=0;i<32;i++){ s+=pavg[(b*32+i)*C_+c]; m=fmaxf(m,pmax[(b*32+i)*C_+c]); }
    avg[b*C_+c]=s*(1.f/4096.f); mx[b*C_+c]=m;
}
__global__ void ca_mlp_kernel(const float* __restrict__ avg, const float* __restrict__ mx,
                              const float* __restrict__ w1, const float* __restrict__ w2,
                              float* __restrict__ ca){
    int b = blockIdx.x;
    __shared__ float ha[16], hm[16];
    int tid = threadIdx.x;
    if(tid<16){
        float sa_=0.f, sm_=0.f;
        const float* w1r = w1 + tid*C_;
        for(int c=0;c<C_;c++){ sa_ += avg[b*C_+c]*w1r[c]; sm_ += mx[b*C_+c]*w1r[c]; }
        ha[tid]=fmaxf(sa_,0.f); hm[tid]=fmaxf(sm_,0.f);
    }
    __syncthreads();
    float s=0.f;
    const float* w2r = w2 + tid*16;
    #pragma unroll
    for(int j=0;j<16;j++) s += (ha[j]+hm[j])*w2r[j];
    ca[b*C_+tid] = sigmoid_f(s);
}
__global__ void smap_kernel(const float* __restrict__ x2, const float* __restrict__ ca,
                            float* __restrict__ smean, float* __restrict__ smax){
    int w = threadIdx.x>>5, lane = threadIdx.x&31;
    int t = blockIdx.x*8 + w;
    int b = t>>12;
    const float* row = x2 + (size_t)t*C_;
    const float* cab = ca + b*C_;
    float s=0.f, m=-1e30f;
    #pragma unroll
    for(int i=0;i<8;i++){ int c=lane+32*i; float v=row[c]*cab[c]; s+=v; m=fmaxf(m,v); }
    #pragma unroll
    for(int o=16;o>0;o>>=1){ s+=__shfl_xor_sync(0xffffffffu,s,o); m=fmaxf(m,__shfl_xor_sync(0xffffffffu,m,o)); }
    if(lane==0){ smean[t]=s*(1.f/C_); smax[t]=m; }
}
__global__ void spconv_kernel(const float* __restrict__ smean, const float* __restrict__ smax,
                              const float* __restrict__ w, const float* __restrict__ bias,
                              float* __restrict__ sa){
    int t = blockIdx.x*256 + threadIdx.x;
    int b = t>>12, n = t&4095;
    int y = n>>6, x = n&63;
    float s = bias[0];
    for(int dy=-3;dy<=3;dy++){
        int yy=y+dy; if(yy<0||yy>=64) continue;
        for(int dx=-3;dx<=3;dx++){
            int xx=x+dx; if(xx<0||xx>=64) continue;
            int nn = b*4096 + yy*64+xx;
            int wi = (dy+3)*7+(dx+3);
            s += smean[nn]*w[wi] + smax[nn]*w[49+wi];
        }
    }
    sa[t] = sigmoid_f(s);
}
__global__ void final_kernel(const float* __restrict__ x2, const float* __restrict__ ca,
                             const float* __restrict__ sa, float* __restrict__ out){
    size_t i = (size_t)blockIdx.x*256 + threadIdx.x;
    int c = (int)(i & 255);
    int t = (int)(i >> 8);
    int b = t >> 12;
    out[i] = x2[i]*ca[b*256+c]*sa[t];
}

// ---------------- host ----------------
static inline void gemm(const float*A,const float*W,const float*bias,const float*a0,
                        const float*a1,float*out,int M,int N,int K){
    dim3 g(N/128, M/128);
    gemm_tf32_kernel<<<g,256>>>(A,W,bias,a0,a1,out,M,N,K);
}

extern "C" void kernel_launch(void* const* d_in, const int* in_sizes, int n_in,
                              void* d_out, int out_size){
    const float* x      = (const float*)d_in[0];
    const float* n1_g   = (const float*)d_in[3];
    const float* n1_b   = (const float*)d_in[4];
    const float* sr_w   = (const float*)d_in[5];
    const float* sr_b   = (const float*)d_in[6];
    const float* an_g   = (const float*)d_in[7];
    const float* an_b   = (const float*)d_in[8];
    const float* qkv_w  = (const float*)d_in[9];
    const float* proj_w = (const float*)d_in[10];
    const float* proj_b = (const float*)d_in[11];
    const float* n2_g   = (const float*)d_in[12];
    const float* n2_b   = (const float*)d_in[13];
    const float* fc1_w  = (const float*)d_in[14];
    const float* fc1_b  = (const float*)d_in[15];
    const float* dw_w   = (const float*)d_in[16];
    const float* dw_b   = (const float*)d_in[17];
    const float* fc2_w  = (const float*)d_in[18];
    const float* fc2_b  = (const float*)d_in[19];
    const float* ca_w1  = (const float*)d_in[20];
    const float* ca_w2  = (const float*)d_in[21];
    const float* sp_w   = (const float*)d_in[22];
    const float* sp_b   = (const float*)d_in[23];
    float* out = (float*)d_out;

    float *xn,*tmp,*xa,*qkv,*ctx,*x1,*f1,*f2,*x2,*qmx,*qrs,*pavg,*pmax,*avg,*mx,*ca,*sme,*smx,*sa;
    cudaGetSymbolAddress((void**)&xn,  g_xn);
    cudaGetSymbolAddress((void**)&tmp, g_tmp);
    cudaGetSymbolAddress((void**)&xa,  g_xa);
    cudaGetSymbolAddress((void**)&qkv, g_qkv);
    cudaGetSymbolAddress((void**)&ctx, g_ctx);
    cudaGetSymbolAddress((void**)&x1,  g_x1);
    cudaGetSymbolAddress((void**)&f1,  g_f1);
    cudaGetSymbolAddress((void**)&f2,  g_f2);
    cudaGetSymbolAddress((void**)&x2,  g_x2);
    cudaGetSymbolAddress((void**)&qmx, g_qmx);
    cudaGetSymbolAddress((void**)&qrs, g_qrs);
    cudaGetSymbolAddress((void**)&pavg,g_pavg);
    cudaGetSymbolAddress((void**)&pmax,g_pmax);
    cudaGetSymbolAddress((void**)&avg, g_avg);
    cudaGetSymbolAddress((void**)&mx,  g_mx);
    cudaGetSymbolAddress((void**)&ca,  g_ca);
    cudaGetSymbolAddress((void**)&sme, g_sme);
    cudaGetSymbolAddress((void**)&smx, g_smx);
    cudaGetSymbolAddress((void**)&sa,  g_sa);

    const int TB = T_/8;

    // ---- attention branch ----
    ln_kernel<<<TB,256>>>(x, n1_g, n1_b, xn);
    dwconv3_kernel4<<<(T_*(C_/4))/256,256>>>(xn, sr_w, sr_b, tmp, C_, 0);
    adapter_kernel<<<TB,256>>>(tmp, xn, an_g, an_b, xa);
    gemm(xa, qkv_w, nullptr, nullptr, nullptr, qkv, T_, 3*C_, C_);
    qcolstats_kernel<<<B_*C_,256>>>(qkv, qmx, qrs);
    softmax_k_kernel<<<T_,256>>>(qkv);
    ctx_kernel<<<B_*HDS,256>>>(qkv, ctx);
    attn_kernel2<<<B_*64,256>>>(qkv, ctx, qmx, qrs, tmp);
    gemm(tmp, proj_w, proj_b, x, xn, x1, T_, C_, C_);

    // ---- MixFFN ----
    ln_kernel<<<TB,256>>>(x1, n2_g, n2_b, xa);
    gemm(xa, fc1_w, fc1_b, nullptr, nullptr, f1, T_, HID, C_);
    dwconv3_kernel4<<<(T_*(HID/4))/256,256>>>(f1, dw_w, dw_b, f2, HID, 1);
    gemm(f2, fc2_w, fc2_b, x1, nullptr, x2, T_, C_, HID);

    // ---- CSDA ----
    ca_stats1<<<B_*32,256>>>(x2, pavg, pmax);
    ca_stats2<<<B_,256>>>(pavg, pmax, avg, mx);
    ca_mlp_kernel<<<B_,256>>>(avg, mx, ca_w1, ca_w2, ca);
    smap_kernel<<<TB,256>>>(x2, ca, sme, smx);
    spconv_kernel<<<T_/256,256>>>(sme, smx, sp_w, sp_b, sa);
    final_kernel<<<(T_*C_)/256,256>>>(x2, ca, sa, out);
}

// round 4
// speedup vs baseline: 2.1796x; 1.4797x over previous
#include <cuda_runtime.h>
#include <cuda_bf16.h>
#include <math.h>
#include <stdint.h>

#define B_    16
#define NTOK  4096
#define C_    256
#define T_    (B_*NTOK)     // 65536 tokens
#define HID   1024
#define HDS   8
#define DH    32

typedef __nv_bfloat16 bf16;
typedef __nv_bfloat162 bf162;

// ---------------- scratch ----------------
__device__ float g_xn  [(size_t)T_*C_];
__device__ float g_tmp [(size_t)T_*C_];
__device__ float g_qkv [(size_t)T_*3*C_];
__device__ float g_ctx [(size_t)B_*HDS*DH*DH];
__device__ float g_x1  [(size_t)T_*C_];
__device__ float g_x2  [(size_t)T_*C_];
__device__ float g_qmx [B_*C_];
__device__ float g_qrs [B_*C_];
__device__ float g_pavg[(size_t)B_*32*C_];
__device__ float g_pmax[(size_t)B_*32*C_];
__device__ float g_avg [B_*C_];
__device__ float g_mx  [B_*C_];
__device__ float g_ca  [B_*C_];
__device__ float g_sme [T_];
__device__ float g_smx [T_];
__device__ float g_sa  [T_];
// bf16 activation buffers
__device__ bf16 g_xa_h [(size_t)T_*C_];
__device__ bf16 g_at_h [(size_t)T_*C_];
__device__ bf16 g_ln2_h[(size_t)T_*C_];
__device__ bf16 g_f1_h [(size_t)T_*HID];
__device__ bf16 g_f2_h [(size_t)T_*HID];
// bf16 weights
__device__ bf16 g_wq_h [3*C_*C_];
__device__ bf16 g_wp_h [C_*C_];
__device__ bf16 g_w1_h [HID*C_];
__device__ bf16 g_w2_h [C_*HID];

__device__ __forceinline__ float gelu_f(float x){
    return 0.5f*x*(1.0f+erff(x*0.7071067811865476f));
}
__device__ __forceinline__ float sigmoid_f(float x){
    return 1.0f/(1.0f+expf(-x));
}
__device__ __forceinline__ void mma_bf16(float* c, const uint32_t* a, const uint32_t* b){
    asm volatile("mma.sync.aligned.m16n8k16.row.col.f32.bf16.bf16.f32 "
        "{%0,%1,%2,%3}, {%4,%5,%6,%7}, {%8,%9}, {%0,%1,%2,%3};\n"
        : "+f"(c[0]),"+f"(c[1]),"+f"(c[2]),"+f"(c[3])
        : "r"(a[0]),"r"(a[1]),"r"(a[2]),"r"(a[3]), "r"(b[0]),"r"(b[1]));
}
__device__ __forceinline__ void cpasync16(uint32_t dst, const void* src){
    asm volatile("cp.async.cg.shared.global [%0], [%1], 16;" :: "r"(dst), "l"(src));
}

// ---------------- fp32 -> bf16 converter ----------------
__global__ void cvt_kernel(const float* __restrict__ in, bf16* __restrict__ out, int n){
    int i = blockIdx.x*256 + threadIdx.x;
    if(i<n) out[i] = __float2bfloat16(in[i]);
}

// ---------------- LayerNorm (fp32 out) ----------------
__global__ void ln_kernel(const float* __restrict__ in, const float* __restrict__ g,
                          const float* __restrict__ bta, float* __restrict__ out){
    int w = threadIdx.x>>5, lane = threadIdx.x&31;
    int t = blockIdx.x*8 + w;
    const float* row = in + (size_t)t*C_;
    float v[8]; float s=0.f, s2=0.f;
    #pragma unroll
    for(int i=0;i<8;i++){ v[i]=row[lane+32*i]; s+=v[i]; s2+=v[i]*v[i]; }
    #pragma unroll
    for(int o=16;o>0;o>>=1){ s+=__shfl_xor_sync(0xffffffffu,s,o); s2+=__shfl_xor_sync(0xffffffffu,s2,o); }
    float mean = s*(1.f/C_);
    float var  = s2*(1.f/C_) - mean*mean;
    float rstd = rsqrtf(var+1e-5f);
    float* orow = out + (size_t)t*C_;
    #pragma unroll
    for(int i=0;i<8;i++){ int c=lane+32*i; orow[c] = (v[i]-mean)*rstd*g[c]+bta[c]; }
}

// ---------------- LayerNorm (bf16 out) ----------------
__global__ void ln_bf16_kernel(const float* __restrict__ in, const float* __restrict__ g,
                               const float* __restrict__ bta, bf16* __restrict__ out){
    int w = threadIdx.x>>5, lane = threadIdx.x&31;
    int t = blockIdx.x*8 + w;
    const float* row = in + (size_t)t*C_;
    float v[8]; float s=0.f, s2=0.f;
    #pragma unroll
    for(int i=0;i<8;i++){ v[i]=row[lane+32*i]; s+=v[i]; s2+=v[i]*v[i]; }
    #pragma unroll
    for(int o=16;o>0;o>>=1){ s+=__shfl_xor_sync(0xffffffffu,s,o); s2+=__shfl_xor_sync(0xffffffffu,s2,o); }
    float mean = s*(1.f/C_);
    float var  = s2*(1.f/C_) - mean*mean;
    float rstd = rsqrtf(var+1e-5f);
    bf16* orow = out + (size_t)t*C_;
    #pragma unroll
    for(int i=0;i<8;i++){ int c=lane+32*i; orow[c] = __float2bfloat16((v[i]-mean)*rstd*g[c]+bta[c]); }
}

// xa_h = bf16( xn + gelu(LN(sr)) )
__global__ void adapter_kernel(const float* __restrict__ sr, const float* __restrict__ xn,
                               const float* __restrict__ g, const float* __restrict__ bta,
                               bf16* __restrict__ out){
    int w = threadIdx.x>>5, lane = threadIdx.x&31;
    int t = blockIdx.x*8 + w;
    const float* row = sr + (size_t)t*C_;
    float v[8]; float s=0.f, s2=0.f;
    #pragma unroll
    for(int i=0;i<8;i++){ v[i]=row[lane+32*i]; s+=v[i]; s2+=v[i]*v[i]; }
    #pragma unroll
    for(int o=16;o>0;o>>=1){ s+=__shfl_xor_sync(0xffffffffu,s,o); s2+=__shfl_xor_sync(0xffffffffu,s2,o); }
    float mean = s*(1.f/C_);
    float var  = s2*(1.f/C_) - mean*mean;
    float rstd = rsqrtf(var+1e-5f);
    const float* xr = xn + (size_t)t*C_;
    bf16* orow = out + (size_t)t*C_;
    #pragma unroll
    for(int i=0;i<8;i++){
        int c=lane+32*i;
        float nv = (v[i]-mean)*rstd*g[c]+bta[c];
        orow[c] = __float2bfloat16(xr[c] + gelu_f(nv));
    }
}

// ---------------- depthwise 3x3 fp32 (SR branch, C=256) ----------------
__global__ void dwconv3_kernel4(const float* __restrict__ in, const float* __restrict__ wt,
                                const float* __restrict__ bias, float* __restrict__ out){
    int idx = blockIdx.x*blockDim.x + threadIdx.x;
    int cg = idx & 63;             // 256/4
    int n  = (idx >> 6) & 4095;
    int b  = idx >> 18;
    int c4 = cg*4;
    int y = n>>6, x = n&63;
    float4 s = *(const float4*)(bias + c4);
    float w[4][9];
    #pragma unroll
    for(int j=0;j<4;j++)
        #pragma unroll
        for(int t=0;t<9;t++) w[j][t] = wt[(c4+j)*9+t];
    #pragma unroll
    for(int dy=-1;dy<=1;dy++){
        int yy=y+dy; if((unsigned)yy>=64u) continue;
        #pragma unroll
        for(int dx=-1;dx<=1;dx++){
            int xx=x+dx; if((unsigned)xx>=64u) continue;
            float4 v = *(const float4*)(in + ((size_t)b*4096 + yy*64+xx)*C_ + c4);
            int t=(dy+1)*3+(dx+1);
            s.x += v.x*w[0][t]; s.y += v.y*w[1][t];
            s.z += v.z*w[2][t]; s.w += v.w*w[3][t];
        }
    }
    *(float4*)(out + ((size_t)b*4096 + n)*C_ + c4) = s;
}

// ---------------- depthwise 3x3 bf16 (FFN, C=1024) + GELU ----------------
__global__ void dwconv3_h_kernel(const bf16* __restrict__ in, const float* __restrict__ wt,
                                 const float* __restrict__ bias, bf16* __restrict__ out){
    int idx = blockIdx.x*blockDim.x + threadIdx.x;
    int cg = idx & 255;            // 1024/4
    int n  = (idx >> 8) & 4095;
    int b  = idx >> 20;
    int c4 = cg*4;
    int y = n>>6, x = n&63;
    float4 bb = *(const float4*)(bias + c4);
    float s0=bb.x, s1=bb.y, s2=bb.z, s3=bb.w;
    float w[4][9];
    #pragma unroll
    for(int j=0;j<4;j++)
        #pragma unroll
        for(int t=0;t<9;t++) w[j][t] = wt[(c4+j)*9+t];
    #pragma unroll
    for(int dy=-1;dy<=1;dy++){
        int yy=y+dy; if((unsigned)yy>=64u) continue;
        #pragma unroll
        for(int dx=-1;dx<=1;dx++){
            int xx=x+dx; if((unsigned)xx>=64u) continue;
            const bf162* p = (const bf162*)(in + ((size_t)b*4096 + yy*64+xx)*HID + c4);
            bf162 v01 = p[0], v23 = p[1];
            int t=(dy+1)*3+(dx+1);
            s0 += __bfloat162float(v01.x)*w[0][t];
            s1 += __bfloat162float(v01.y)*w[1][t];
            s2 += __bfloat162float(v23.x)*w[2][t];
            s3 += __bfloat162float(v23.y)*w[3][t];
        }
    }
    bf162* o = (bf162*)(out + ((size_t)b*4096 + n)*HID + c4);
    o[0] = __floats2bfloat162_rn(gelu_f(s0), gelu_f(s1));
    o[1] = __floats2bfloat162_rn(gelu_f(s2), gelu_f(s3));
}

// ---------------- bf16 tensor-core GEMM: out = A @ W^T (+bias)(+add0)(+add1) ----------------
// A[M,K], W[N,K] bf16 row-major. Tile 128x128x32, 2-stage cp.async pipeline.
// 8 warps (2M x 4N), warp tile 64x32, mma.m16n8k16.
__global__ __launch_bounds__(256,1) void gemm_bf16_kernel(
    const bf16* __restrict__ A, const bf16* __restrict__ W,
    const float* __restrict__ bias, const float* __restrict__ add0,
    const float* __restrict__ add1, float* __restrict__ out,
    bf16* __restrict__ outh, int M, int N, int K){
    // row-major tiles, 128 rows x 16 data words (+4 pad) per row
    __shared__ uint32_t As[2][128*20];
    __shared__ uint32_t Ws[2][128*20];
    int tid = threadIdx.x;
    int bm = blockIdx.y*128, bn = blockIdx.x*128;
    int wid = tid>>5, lane = tid&31;
    int wm = wid&1, wn = wid>>1;
    int g = lane>>2, tg = lane&3;

    float acc[4][4][4];
    #pragma unroll
    for(int mi=0;mi<4;mi++)
        #pragma unroll
        for(int ni=0;ni<4;ni++)
            #pragma unroll
            for(int r=0;r<4;r++) acc[mi][ni][r]=0.f;

    // loader mapping: thread handles rows r0 and r0+64, 16B segment seg
    int r0  = tid>>2;
    int seg = tid&3;
    const bf16* Ag0 = A + (size_t)(bm + r0)*K + seg*8;
    const bf16* Ag1 = A + (size_t)(bm + r0+64)*K + seg*8;
    const bf16* Wg0 = W + (size_t)(bn + r0)*K + seg*8;
    const bf16* Wg1 = W + (size_t)(bn + r0+64)*K + seg*8;
    uint32_t a_smem = (uint32_t)__cvta_generic_to_shared(&As[0][0]);
    uint32_t w_smem = (uint32_t)__cvta_generic_to_shared(&Ws[0][0]);
    int d0 = (r0*20 + seg*4)*4;        // byte offsets
    int d1 = ((r0+64)*20 + seg*4)*4;

    auto load_stage = [&](int s, int k0){
        uint32_t ab = a_smem + s*(128*20*4);
        uint32_t wb = w_smem + s*(128*20*4);
        cpasync16(ab + d0, Ag0 + k0);
        cpasync16(ab + d1, Ag1 + k0);
        cpasync16(wb + d0, Wg0 + k0);
        cpasync16(wb + d1, Wg1 + k0);
    };

    load_stage(0, 0);
    asm volatile("cp.async.commit_group;");

    int nst = K/32;
    int ar_base = wm*64;
    int wc_base = wn*32;
    for(int i=0;i<nst;i++){
        if(i+1<nst) load_stage((i+1)&1, (i+1)*32);
        asm volatile("cp.async.commit_group;");
        asm volatile("cp.async.wait_group 1;");
        __syncthreads();
        const uint32_t* asb = As[i&1];
        const uint32_t* wsb = Ws[i&1];
        #pragma unroll
        for(int k16=0;k16<2;k16++){
            int kw = k16*8;
            uint32_t af[4][4], bf[4][2];
            #pragma unroll
            for(int mi=0;mi<4;mi++){
                int r = ar_base + mi*16 + g;
                af[mi][0]=asb[r*20     + kw+tg];
                af[mi][1]=asb[(r+8)*20 + kw+tg];
                af[mi][2]=asb[r*20     + kw+tg+4];
                af[mi][3]=asb[(r+8)*20 + kw+tg+4];
            }
            #pragma unroll
            for(int ni=0;ni<4;ni++){
                int c = wc_base + ni*8 + g;
                bf[ni][0]=wsb[c*20 + kw+tg];
                bf[ni][1]=wsb[c*20 + kw+tg+4];
            }
            #pragma unroll
            for(int mi=0;mi<4;mi++)
                #pragma unroll
                for(int ni=0;ni<4;ni++)
                    mma_bf16(acc[mi][ni], af[mi], bf[ni]);
        }
        __syncthreads();
    }

    // epilogue: c0:(g, tg*2) c1:(g, tg*2+1) c2:(g+8, tg*2) c3:(g+8, tg*2+1)
    #pragma unroll
    for(int mi=0;mi<4;mi++){
        int row0 = bm + wm*64 + mi*16 + g;
        #pragma unroll
        for(int ni=0;ni<4;ni++){
            int col = bn + wn*32 + ni*8 + tg*2;
            size_t o0 = (size_t)row0*N + col;
            size_t o1 = (size_t)(row0+8)*N + col;
            float v0=acc[mi][ni][0], v1=acc[mi][ni][1], v2=acc[mi][ni][2], v3=acc[mi][ni][3];
            if(bias){ float b0=bias[col], b1=bias[col+1]; v0+=b0; v1+=b1; v2+=b0; v3+=b1; }
            if(add0){ v0+=add0[o0]; v1+=add0[o0+1]; v2+=add0[o1]; v3+=add0[o1+1]; }
            if(add1){ v0+=add1[o0]; v1+=add1[o0+1]; v2+=add1[o1]; v3+=add1[o1+1]; }
            if(outh){
                *(bf162*)(outh + o0) = __floats2bfloat162_rn(v0, v1);
                *(bf162*)(outh + o1) = __floats2bfloat162_rn(v2, v3);
            }else{
                out[o0]=v0; out[o0+1]=v1; out[o1]=v2; out[o1+1]=v3;
            }
        }
    }
}

// ---------------- q column stats ----------------
__global__ void qcolstats_kernel(const float* __restrict__ qkv,
                                 float* __restrict__ qmx, float* __restrict__ qrs){
    int b   = blockIdx.x>>8;
    int col = blockIdx.x&255;
    int tid = threadIdx.x;
    __shared__ float red[256];
    float v[16]; float mx=-1e30f;
    size_t base = (size_t)b*NTOK*768 + col;
    #pragma unroll
    for(int i=0;i<16;i++){ v[i]=qkv[base + (size_t)(tid+i*256)*768]; mx=fmaxf(mx,v[i]); }
    red[tid]=mx; __syncthreads();
    for(int s=128;s>0;s>>=1){ if(tid<s) red[tid]=fmaxf(red[tid],red[tid+s]); __syncthreads(); }
    mx = red[0]; __syncthreads();
    float sum=0.f;
    #pragma unroll
    for(int i=0;i<16;i++) sum += expf(v[i]-mx);
    red[tid]=sum; __syncthreads();
    for(int s=128;s>0;s>>=1){ if(tid<s) red[tid]+=red[tid+s]; __syncthreads(); }
    if(tid==0){ qmx[b*C_+col]=mx; qrs[b*C_+col]=1.f/red[0]; }
}

// ---------------- k softmax over head dim ----------------
__global__ void softmax_k_kernel(float* __restrict__ qkv){
    int wp = threadIdx.x>>5, lane = threadIdx.x&31;
    int p = blockIdx.x*8 + wp;
    int t = p>>3, h = p&7;
    size_t idx = (size_t)t*768 + 256 + h*32 + lane;
    float v = qkv[idx];
    float mx = v;
    #pragma unroll
    for(int o=16;o>0;o>>=1) mx = fmaxf(mx, __shfl_xor_sync(0xffffffffu,mx,o));
    float e = expf(v-mx), s=e;
    #pragma unroll
    for(int o=16;o>0;o>>=1) s += __shfl_xor_sync(0xffffffffu,s,o);
    qkv[idx] = e/s;
}

// ---------------- ctx[b,h,d,e] = sum_n k[n,d]*v[n,e] ----------------
__global__ __launch_bounds__(256) void ctx_kernel(const float* __restrict__ qkv, float* __restrict__ ctx){
    int b = blockIdx.x>>3, h = blockIdx.x&7;
    __shared__ float ks[32][33], vs[32][33];
    int tid = threadIdx.x;
    int row = tid>>3, colq = (tid&7)*4;
    int j = tid&31, i0 = (tid>>5)*4;
    size_t offK = 256 + h*32;
    float acc[4]={0,0,0,0};
    for(int n0=0;n0<NTOK;n0+=32){
        size_t rbase = ((size_t)b*NTOK + n0 + row)*768;
        float4 kv = *(const float4*)(qkv + rbase + offK + colq);
        float4 vv = *(const float4*)(qkv + rbase + offK + 256 + colq);
        ks[row][colq+0]=kv.x; ks[row][colq+1]=kv.y; ks[row][colq+2]=kv.z; ks[row][colq+3]=kv.w;
        vs[row][colq+0]=vv.x; vs[row][colq+1]=vv.y; vs[row][colq+2]=vv.z; vs[row][colq+3]=vv.w;
        __syncthreads();
        #pragma unroll 8
        for(int nn=0;nn<32;nn++){
            float vj = vs[nn][j];
            acc[0] = fmaf(ks[nn][i0+0], vj, acc[0]);
            acc[1] = fmaf(ks[nn][i0+1], vj, acc[1]);
            acc[2] = fmaf(ks[nn][i0+2], vj, acc[2]);
            acc[3] = fmaf(ks[nn][i0+3], vj, acc[3]);
        }
        __syncthreads();
    }
    float* cb = ctx + (size_t)(b*8+h)*1024;
    #pragma unroll
    for(int r=0;r<4;r++) cb[(i0+r)*32 + j] = acc[r];
}

// ---------------- fused q-softmax + attn (bf16 out) ----------------
__global__ __launch_bounds__(256) void attn_kernel2(const float* __restrict__ qkv,
                                                    const float* __restrict__ ctx,
                                                    const float* __restrict__ qmx,
                                                    const float* __restrict__ qrs,
                                                    bf16* __restrict__ out){
    __shared__ float cs[8192];
    __shared__ float qs[8][256];
    int b = blockIdx.x>>6;
    int grp = blockIdx.x&63;
    int tid = threadIdx.x;
    #pragma unroll
    for(int i=0;i<32;i++) cs[tid + i*256] = ctx[(size_t)b*8192 + tid + i*256];
    float cmx = qmx[b*C_+tid];
    float crs = qrs[b*C_+tid];
    int h = tid>>5, dd = tid&31;
    const float* ch = cs + h*1024;
    __syncthreads();
    for(int t8=0;t8<8;t8++){
        size_t t0 = (size_t)b*NTOK + grp*64 + t8*8;
        #pragma unroll
        for(int i=0;i<8;i++)
            qs[i][tid] = expf(qkv[(t0+i)*768 + tid] - cmx)*crs;
        __syncthreads();
        #pragma unroll
        for(int i=0;i<8;i++){
            float s = 0.f;
            #pragma unroll
            for(int e=0;e<32;e++) s = fmaf(qs[i][h*32+e], ch[e*32+dd], s);
            out[(t0+i)*256 + tid] = __float2bfloat16(s);
        }
        __syncthreads();
    }
}

// ---------------- CSDA ----------------
__global__ void ca_stats1(const float* __restrict__ x, float* __restrict__ pavg, float* __restrict__ pmax){
    int b = blockIdx.x>>5, ch = blockIdx.x&31;
    int c = threadIdx.x;
    float s=0.f, m=-1e30f;
    for(int i=0;i<128;i++){
        float v = x[((size_t)b*NTOK + ch*128+i)*C_ + c];
        s += v; m = fmaxf(m,v);
    }
    pavg[(b*32+ch)*C_+c]=s; pmax[(b*32+ch)*C_+c]=m;
}
__global__ void ca_stats2(const float* __restrict__ pavg, const float* __restrict__ pmax,
                          float* __restrict__ avg, float* __restrict__ mx){
    int b=blockIdx.x; int c=threadIdx.x;
    float s=0.f, m=-1e30f;
    for(int i=0;i<32;i++){ s+=pavg[(b*32+i)*C_+c]; m=fmaxf(m,pmax[(b*32+i)*C_+c]); }
    avg[b*C_+c]=s*(1.f/4096.f); mx[b*C_+c]=m;
}
__global__ void ca_mlp_kernel(const float* __restrict__ avg, const float* __restrict__ mx,
                              const float* __restrict__ w1, const float* __restrict__ w2,
                              float* __restrict__ ca){
    int b = blockIdx.x;
    __shared__ float ha[16], hm[16];
    int tid = threadIdx.x;
    if(tid<16){
        float sa_=0.f, sm_=0.f;
        const float* w1r = w1 + tid*C_;
        for(int c=0;c<C_;c++){ sa_ += avg[b*C_+c]*w1r[c]; sm_ += mx[b*C_+c]*w1r[c]; }
        ha[tid]=fmaxf(sa_,0.f); hm[tid]=fmaxf(sm_,0.f);
    }
    __syncthreads();
    float s=0.f;
    const float* w2r = w2 + tid*16;
    #pragma unroll
    for(int j=0;j<16;j++) s += (ha[j]+hm[j])*w2r[j];
    ca[b*C_+tid] = sigmoid_f(s);
}
__global__ void smap_kernel(const float* __restrict__ x2, const float* __restrict__ ca,
                            float* __restrict__ smean, float* __restrict__ smax){
    int w = threadIdx.x>>5, lane = threadIdx.x&31;
    int t = blockIdx.x*8 + w;
    int b = t>>12;
    const float* row = x2 + (size_t)t*C_;
    const float* cab = ca + b*C_;
    float s=0.f, m=-1e30f;
    #pragma unroll
    for(int i=0;i<8;i++){ int c=lane+32*i; float v=row[c]*cab[c]; s+=v; m=fmaxf(m,v); }
    #pragma unroll
    for(int o=16;o>0;o>>=1){ s+=__shfl_xor_sync(0xffffffffu,s,o); m=fmaxf(m,__shfl_xor_sync(0xffffffffu,m,o)); }
    if(lane==0){ smean[t]=s*(1.f/C_); smax[t]=m; }
}
__global__ void spconv_kernel(const float* __restrict__ smean, const float* __restrict__ smax,
                              const float* __restrict__ w, const float* __restrict__ bias,
                              float* __restrict__ sa){
    int t = blockIdx.x*256 + threadIdx.x;
    int b = t>>12, n = t&4095;
    int y = n>>6, x = n&63;
    float s = bias[0];
    for(int dy=-3;dy<=3;dy++){
        int yy=y+dy; if(yy<0||yy>=64) continue;
        for(int dx=-3;dx<=3;dx++){
            int xx=x+dx; if(xx<0||xx>=64) continue;
            int nn = b*4096 + yy*64+xx;
            int wi = (dy+3)*7+(dx+3);
            s += smean[nn]*w[wi] + smax[nn]*w[49+wi];
        }
    }
    sa[t] = sigmoid_f(s);
}
__global__ void final_kernel(const float* __restrict__ x2, const float* __restrict__ ca,
                             const float* __restrict__ sa, float* __restrict__ out){
    size_t i = (size_t)blockIdx.x*256 + threadIdx.x;
    int c = (int)(i & 255);
    int t = (int)(i >> 8);
    int b = t >> 12;
    out[i] = x2[i]*ca[b*256+c]*sa[t];
}

// ---------------- host ----------------
static inline void gemm(const bf16*A,const bf16*W,const float*bias,const float*a0,
                        const float*a1,float*out,bf16*outh,int M,int N,int K){
    dim3 g(N/128, M/128);
    gemm_bf16_kernel<<<g,256>>>(A,W,bias,a0,a1,out,outh,M,N,K);
}

extern "C" void kernel_launch(void* const* d_in, const int* in_sizes, int n_in,
                              void* d_out, int out_size){
    const float* x      = (const float*)d_in[0];
    const float* n1_g   = (const float*)d_in[3];
    const float* n1_b   = (const float*)d_in[4];
    const float* sr_w   = (const float*)d_in[5];
    const float* sr_b   = (const float*)d_in[6];
    const float* an_g   = (const float*)d_in[7];
    const float* an_b   = (const float*)d_in[8];
    const float* qkv_w  = (const float*)d_in[9];
    const float* proj_w = (const float*)d_in[10];
    const float* proj_b = (const float*)d_in[11];
    const float* n2_g   = (const float*)d_in[12];
    const float* n2_b   = (const float*)d_in[13];
    const float* fc1_w  = (const float*)d_in[14];
    const float* fc1_b  = (const float*)d_in[15];
    const float* dw_w   = (const float*)d_in[16];
    const float* dw_b   = (const float*)d_in[17];
    const float* fc2_w  = (const float*)d_in[18];
    const float* fc2_b  = (const float*)d_in[19];
    const float* ca_w1  = (const float*)d_in[20];
    const float* ca_w2  = (const float*)d_in[21];
    const float* sp_w   = (const float*)d_in[22];
    const float* sp_b   = (const float*)d_in[23];
    float* out = (float*)d_out;

    float *xn,*tmp,*qkv,*ctx,*x1,*x2,*qmx,*qrs,*pavg,*pmax,*avg,*mx,*ca,*sme,*smx,*sa;
    bf16 *xa_h,*at_h,*ln2_h,*f1_h,*f2_h,*wq_h,*wp_h,*w1_h,*w2_h;
    cudaGetSymbolAddress((void**)&xn,  g_xn);
    cudaGetSymbolAddress((void**)&tmp, g_tmp);
    cudaGetSymbolAddress((void**)&qkv, g_qkv);
    cudaGetSymbolAddress((void**)&ctx, g_ctx);
    cudaGetSymbolAddress((void**)&x1,  g_x1);
    cudaGetSymbolAddress((void**)&x2,  g_x2);
    cudaGetSymbolAddress((void**)&qmx, g_qmx);
    cudaGetSymbolAddress((void**)&qrs, g_qrs);
    cudaGetSymbolAddress((void**)&pavg,g_pavg);
    cudaGetSymbolAddress((void**)&pmax,g_pmax);
    cudaGetSymbolAddress((void**)&avg, g_avg);
    cudaGetSymbolAddress((void**)&mx,  g_mx);
    cudaGetSymbolAddress((void**)&ca,  g_ca);
    cudaGetSymbolAddress((void**)&sme, g_sme);
    cudaGetSymbolAddress((void**)&smx, g_smx);
    cudaGetSymbolAddress((void**)&sa,  g_sa);
    cudaGetSymbolAddress((void**)&xa_h, g_xa_h);
    cudaGetSymbolAddress((void**)&at_h, g_at_h);
    cudaGetSymbolAddress((void**)&ln2_h,g_ln2_h);
    cudaGetSymbolAddress((void**)&f1_h, g_f1_h);
    cudaGetSymbolAddress((void**)&f2_h, g_f2_h);
    cudaGetSymbolAddress((void**)&wq_h, g_wq_h);
    cudaGetSymbolAddress((void**)&wp_h, g_wp_h);
    cudaGetSymbolAddress((void**)&w1_h, g_w1_h);
    cudaGetSymbolAddress((void**)&w2_h, g_w2_h);

    const int TB = T_/8;

    // ---- weight conversion (tiny) ----
    cvt_kernel<<<(3*C_*C_)/256,256>>>(qkv_w,  wq_h, 3*C_*C_);
    cvt_kernel<<<(C_*C_)/256,256>>>  (proj_w, wp_h, C_*C_);
    cvt_kernel<<<(HID*C_)/256,256>>> (fc1_w,  w1_h, HID*C_);
    cvt_kernel<<<(C_*HID)/256,256>>> (fc2_w,  w2_h, C_*HID);

    // ---- attention branch ----
    ln_kernel<<<TB,256>>>(x, n1_g, n1_b, xn);
    dwconv3_kernel4<<<(T_*(C_/4))/256,256>>>(xn, sr_w, sr_b, tmp);
    adapter_kernel<<<TB,256>>>(tmp, xn, an_g, an_b, xa_h);
    gemm(xa_h, wq_h, nullptr, nullptr, nullptr, qkv, nullptr, T_, 3*C_, C_);
    qcolstats_kernel<<<B_*C_,256>>>(qkv, qmx, qrs);
    softmax_k_kernel<<<T_,256>>>(qkv);
    ctx_kernel<<<B_*HDS,256>>>(qkv, ctx);
    attn_kernel2<<<B_*64,256>>>(qkv, ctx, qmx, qrs, at_h);
    gemm(at_h, wp_h, proj_b, x, xn, x1, nullptr, T_, C_, C_);

    // ---- MixFFN ----
    ln_bf16_kernel<<<TB,256>>>(x1, n2_g, n2_b, ln2_h);
    gemm(ln2_h, w1_h, fc1_b, nullptr, nullptr, nullptr, f1_h, T_, HID, C_);
    dwconv3_h_kernel<<<(T_*(HID/4))/256,256>>>(f1_h, dw_w, dw_b, f2_h);
    gemm(f2_h, w2_h, fc2_b, x1, nullptr, x2, nullptr, T_, C_, HID);

    // ---- CSDA ----
    ca_stats1<<<B_*32,256>>>(x2, pavg, pmax);
    ca_stats2<<<B_,256>>>(pavg, pmax, avg, mx);
    ca_mlp_kernel<<<B_,256>>>(avg, mx, ca_w1, ca_w2, ca);
    smap_kernel<<<TB,256>>>(x2, ca, sme, smx);
    spconv_kernel<<<T_/256,256>>>(sme, smx, sp_w, sp_b, sa);
    final_kernel<<<(T_*C_)/256,256>>>(x2, ca, sa, out);
}

// round 8
// speedup vs baseline: 2.2655x; 1.0394x over previous
#include <cuda_runtime.h>
#include <cuda_bf16.h>
#include <math.h>
#include <stdint.h>

#define B_    16
#define NTOK  4096
#define C_    256
#define T_    (B_*NTOK)     // 65536 tokens
#define HID   1024
#define HDS   8
#define DH    32

typedef __nv_bfloat16 bf16;
typedef __nv_bfloat162 bf162;

// ---------------- scratch ----------------
__device__ float g_xn  [(size_t)T_*C_];
__device__ float g_tmp [(size_t)T_*C_];
__device__ float g_q   [(size_t)T_*C_];
__device__ float g_ctx [(size_t)B_*HDS*DH*DH];
__device__ float g_x1  [(size_t)T_*C_];
__device__ float g_x2  [(size_t)T_*C_];
__device__ float g_qmx [B_*C_];
__device__ float g_qrs [B_*C_];
__device__ float g_pavg[(size_t)B_*32*C_];
__device__ float g_pmax[(size_t)B_*32*C_];
__device__ float g_avg [B_*C_];
__device__ float g_mx  [B_*C_];
__device__ float g_ca  [B_*C_];
__device__ float g_sme [T_];
__device__ float g_smx [T_];
__device__ float g_sa  [T_];
// bf16 buffers
__device__ bf16 g_xa_h [(size_t)T_*C_];
__device__ bf16 g_kv_h [(size_t)T_*2*C_];   // [t, 0:256)=softmax(k), [256:512)=v
__device__ bf16 g_at_h [(size_t)T_*C_];
__device__ bf16 g_ln2_h[(size_t)T_*C_];
__device__ bf16 g_f1_h [(size_t)T_*HID];
__device__ bf16 g_f2_h [(size_t)T_*HID];
// bf16 weights
__device__ bf16 g_wq_h [3*C_*C_];
__device__ bf16 g_wp_h [C_*C_];
__device__ bf16 g_w1_h [HID*C_];
__device__ bf16 g_w2_h [C_*HID];

__device__ __forceinline__ float gelu_f(float x){
    return 0.5f*x*(1.0f+erff(x*0.7071067811865476f));
}
__device__ __forceinline__ float sigmoid_f(float x){
    return 1.0f/(1.0f+expf(-x));
}
__device__ __forceinline__ void mma_bf16(float* c, const uint32_t* a, const uint32_t* b){
    asm volatile("mma.sync.aligned.m16n8k16.row.col.f32.bf16.bf16.f32 "
        "{%0,%1,%2,%3}, {%4,%5,%6,%7}, {%8,%9}, {%0,%1,%2,%3};\n"
        : "+f"(c[0]),"+f"(c[1]),"+f"(c[2]),"+f"(c[3])
        : "r"(a[0]),"r"(a[1]),"r"(a[2]),"r"(a[3]), "r"(b[0]),"r"(b[1]));
}
__device__ __forceinline__ void cpasync16(uint32_t dst, const void* src){
    asm volatile("cp.async.cg.shared.global [%0], [%1], 16;" :: "r"(dst), "l"(src));
}

// ---------------- fp32 -> bf16 converter ----------------
__global__ void cvt_kernel(const float* __restrict__ in, bf16* __restrict__ out, int n){
    int i = blockIdx.x*256 + threadIdx.x;
    if(i<n) out[i] = __float2bfloat16(in[i]);
}

// ---------------- LayerNorm (fp32 out) ----------------
__global__ void ln_kernel(const float* __restrict__ in, const float* __restrict__ g,
                          const float* __restrict__ bta, float* __restrict__ out){
    int w = threadIdx.x>>5, lane = threadIdx.x&31;
    int t = blockIdx.x*8 + w;
    const float* row = in + (size_t)t*C_;
    float v[8]; float s=0.f, s2=0.f;
    #pragma unroll
    for(int i=0;i<8;i++){ v[i]=row[lane+32*i]; s+=v[i]; s2+=v[i]*v[i]; }
    #pragma unroll
    for(int o=16;o>0;o>>=1){ s+=__shfl_xor_sync(0xffffffffu,s,o); s2+=__shfl_xor_sync(0xffffffffu,s2,o); }
    float mean = s*(1.f/C_);
    float var  = s2*(1.f/C_) - mean*mean;
    float rstd = rsqrtf(var+1e-5f);
    float* orow = out + (size_t)t*C_;
    #pragma unroll
    for(int i=0;i<8;i++){ int c=lane+32*i; orow[c] = (v[i]-mean)*rstd*g[c]+bta[c]; }
}

// ---------------- LayerNorm (bf16 out) ----------------
__global__ void ln_bf16_kernel(const float* __restrict__ in, const float* __restrict__ g,
                               const float* __restrict__ bta, bf16* __restrict__ out){
    int w = threadIdx.x>>5, lane = threadIdx.x&31;
    int t = blockIdx.x*8 + w;
    const float* row = in + (size_t)t*C_;
    float v[8]; float s=0.f, s2=0.f;
    #pragma unroll
    for(int i=0;i<8;i++){ v[i]=row[lane+32*i]; s+=v[i]; s2+=v[i]*v[i]; }
    #pragma unroll
    for(int o=16;o>0;o>>=1){ s+=__shfl_xor_sync(0xffffffffu,s,o); s2+=__shfl_xor_sync(0xffffffffu,s2,o); }
    float mean = s*(1.f/C_);
    float var  = s2*(1.f/C_) - mean*mean;
    float rstd = rsqrtf(var+1e-5f);
    bf16* orow = out + (size_t)t*C_;
    #pragma unroll
    for(int i=0;i<8;i++){ int c=lane+32*i; orow[c] = __float2bfloat16((v[i]-mean)*rstd*g[c]+bta[c]); }
}

// xa_h = bf16( xn + gelu(LN(sr)) )
__global__ void adapter_kernel(const float* __restrict__ sr, const float* __restrict__ xn,
                               const float* __restrict__ g, const float* __restrict__ bta,
                               bf16* __restrict__ out){
    int w = threadIdx.x>>5, lane = threadIdx.x&31;
    int t = blockIdx.x*8 + w;
    const float* row = sr + (size_t)t*C_;
    float v[8]; float s=0.f, s2=0.f;
    #pragma unroll
    for(int i=0;i<8;i++){ v[i]=row[lane+32*i]; s+=v[i]; s2+=v[i]*v[i]; }
    #pragma unroll
    for(int o=16;o>0;o>>=1){ s+=__shfl_xor_sync(0xffffffffu,s,o); s2+=__shfl_xor_sync(0xffffffffu,s2,o); }
    float mean = s*(1.f/C_);
    float var  = s2*(1.f/C_) - mean*mean;
    float rstd = rsqrtf(var+1e-5f);
    const float* xr = xn + (size_t)t*C_;
    bf16* orow = out + (size_t)t*C_;
    #pragma unroll
    for(int i=0;i<8;i++){
        int c=lane+32*i;
        float nv = (v[i]-mean)*rstd*g[c]+bta[c];
        orow[c] = __float2bfloat16(xr[c] + gelu_f(nv));
    }
}

// ---------------- depthwise 3x3 fp32 (SR branch, C=256) ----------------
__global__ void dwconv3_kernel4(const float* __restrict__ in, const float* __restrict__ wt,
                                const float* __restrict__ bias, float* __restrict__ out){
    int idx = blockIdx.x*blockDim.x + threadIdx.x;
    int cg = idx & 63;
    int n  = (idx >> 6) & 4095;
    int b  = idx >> 18;
    int c4 = cg*4;
    int y = n>>6, x = n&63;
    float4 s = *(const float4*)(bias + c4);
    float w[4][9];
    #pragma unroll
    for(int j=0;j<4;j++)
        #pragma unroll
        for(int t=0;t<9;t++) w[j][t] = wt[(c4+j)*9+t];
    #pragma unroll
    for(int dy=-1;dy<=1;dy++){
        int yy=y+dy; if((unsigned)yy>=64u) continue;
        #pragma unroll
        for(int dx=-1;dx<=1;dx++){
            int xx=x+dx; if((unsigned)xx>=64u) continue;
            float4 v = *(const float4*)(in + ((size_t)b*4096 + yy*64+xx)*C_ + c4);
            int t=(dy+1)*3+(dx+1);
            s.x += v.x*w[0][t]; s.y += v.y*w[1][t];
            s.z += v.z*w[2][t]; s.w += v.w*w[3][t];
        }
    }
    *(float4*)(out + ((size_t)b*4096 + n)*C_ + c4) = s;
}

// ---------------- depthwise 3x3 bf16 (FFN, C=1024) + GELU ----------------
__global__ void dwconv3_h_kernel(const bf16* __restrict__ in, const float* __restrict__ wt,
                                 const float* __restrict__ bias, bf16* __restrict__ out){
    int idx = blockIdx.x*blockDim.x + threadIdx.x;
    int cg = idx & 255;
    int n  = (idx >> 8) & 4095;
    int b  = idx >> 20;
    int c4 = cg*4;
    int y = n>>6, x = n&63;
    float4 bb = *(const float4*)(bias + c4);
    float s0=bb.x, s1=bb.y, s2=bb.z, s3=bb.w;
    float w[4][9];
    #pragma unroll
    for(int j=0;j<4;j++)
        #pragma unroll
        for(int t=0;t<9;t++) w[j][t] = wt[(c4+j)*9+t];
    #pragma unroll
    for(int dy=-1;dy<=1;dy++){
        int yy=y+dy; if((unsigned)yy>=64u) continue;
        #pragma unroll
        for(int dx=-1;dx<=1;dx++){
            int xx=x+dx; if((unsigned)xx>=64u) continue;
            const bf162* p = (const bf162*)(in + ((size_t)b*4096 + yy*64+xx)*HID + c4);
            bf162 v01 = p[0], v23 = p[1];
            int t=(dy+1)*3+(dx+1);
            s0 += __bfloat162float(v01.x)*w[0][t];
            s1 += __bfloat162float(v01.y)*w[1][t];
            s2 += __bfloat162float(v23.x)*w[2][t];
            s3 += __bfloat162float(v23.y)*w[3][t];
        }
    }
    bf162* o = (bf162*)(out + ((size_t)b*4096 + n)*HID + c4);
    o[0] = __floats2bfloat162_rn(gelu_f(s0), gelu_f(s1));
    o[1] = __floats2bfloat162_rn(gelu_f(s2), gelu_f(s3));
}

// ================== shared GEMM mainloop (macro) ==================
// defines acc[4][4][4], bm,bn,wm,wn,g,tg after running; 128x128x32 tiles.
#define GEMM_MAINLOOP(A, W, M, N, K) \
    __shared__ uint32_t As[2][128*20]; \
    __shared__ uint32_t Ws[2][128*20]; \
    int tid = threadIdx.x; \
    int bm = blockIdx.y*128, bn = blockIdx.x*128; \
    int wid = tid>>5, lane = tid&31; \
    int wm = wid&1, wn = wid>>1; \
    int g = lane>>2, tg = lane&3; \
    float acc[4][4][4]; \
    _Pragma("unroll") \
    for(int mi=0;mi<4;mi++) \
        _Pragma("unroll") \
        for(int ni=0;ni<4;ni++) \
            _Pragma("unroll") \
            for(int r=0;r<4;r++) acc[mi][ni][r]=0.f; \
    int r0  = tid>>2; \
    int seg = tid&3; \
    const bf16* Ag0 = A + (size_t)(bm + r0)*K + seg*8; \
    const bf16* Ag1 = A + (size_t)(bm + r0+64)*K + seg*8; \
    const bf16* Wg0 = W + (size_t)(bn + r0)*K + seg*8; \
    const bf16* Wg1 = W + (size_t)(bn + r0+64)*K + seg*8; \
    uint32_t a_smem = (uint32_t)__cvta_generic_to_shared(&As[0][0]); \
    uint32_t w_smem = (uint32_t)__cvta_generic_to_shared(&Ws[0][0]); \
    int d0 = (r0*20 + seg*4)*4; \
    int d1 = ((r0+64)*20 + seg*4)*4; \
    { \
        uint32_t ab = a_smem, wb = w_smem; \
        cpasync16(ab + d0, Ag0); cpasync16(ab + d1, Ag1); \
        cpasync16(wb + d0, Wg0); cpasync16(wb + d1, Wg1); \
    } \
    asm volatile("cp.async.commit_group;"); \
    int nst = K/32; \
    int ar_base = wm*64; \
    int wc_base = wn*32; \
    for(int i=0;i<nst;i++){ \
        if(i+1<nst){ \
            int s=(i+1)&1, k0=(i+1)*32; \
            uint32_t ab = a_smem + s*(128*20*4); \
            uint32_t wb = w_smem + s*(128*20*4); \
            cpasync16(ab + d0, Ag0 + k0); cpasync16(ab + d1, Ag1 + k0); \
            cpasync16(wb + d0, Wg0 + k0); cpasync16(wb + d1, Wg1 + k0); \
        } \
        asm volatile("cp.async.commit_group;"); \
        asm volatile("cp.async.wait_group 1;"); \
        __syncthreads(); \
        const uint32_t* asb = As[i&1]; \
        const uint32_t* wsb = Ws[i&1]; \
        _Pragma("unroll") \
        for(int k16=0;k16<2;k16++){ \
            int kw = k16*8; \
            uint32_t af[4][4], bfr[4][2]; \
            _Pragma("unroll") \
            for(int mi=0;mi<4;mi++){ \
                int r = ar_base + mi*16 + g; \
                af[mi][0]=asb[r*20     + kw+tg]; \
                af[mi][1]=asb[(r+8)*20 + kw+tg]; \
                af[mi][2]=asb[r*20     + kw+tg+4]; \
                af[mi][3]=asb[(r+8)*20 + kw+tg+4]; \
            } \
            _Pragma("unroll") \
            for(int ni=0;ni<4;ni++){ \
                int c = wc_base + ni*8 + g; \
                bfr[ni][0]=wsb[c*20 + kw+tg]; \
                bfr[ni][1]=wsb[c*20 + kw+tg+4]; \
            } \
            _Pragma("unroll") \
            for(int mi=0;mi<4;mi++) \
                _Pragma("unroll") \
                for(int ni=0;ni<4;ni++) \
                    mma_bf16(acc[mi][ni], af[mi], bfr[ni]); \
        } \
        __syncthreads(); \
    }

// ---------------- generic bf16 GEMM: out = A @ W^T (+bias)(+add0)(+add1) ----------------
__global__ __launch_bounds__(256,1) void gemm_bf16_kernel(
    const bf16* __restrict__ A, const bf16* __restrict__ W,
    const float* __restrict__ bias, const float* __restrict__ add0,
    const float* __restrict__ add1, float* __restrict__ out,
    bf16* __restrict__ outh, int M, int N, int K){
    GEMM_MAINLOOP(A, W, M, N, K)
    #pragma unroll
    for(int mi=0;mi<4;mi++){
        int row0 = bm + wm*64 + mi*16 + g;
        #pragma unroll
        for(int ni=0;ni<4;ni++){
            int col = bn + wn*32 + ni*8 + tg*2;
            size_t o0 = (size_t)row0*N + col;
            size_t o1 = (size_t)(row0+8)*N + col;
            float v0=acc[mi][ni][0], v1=acc[mi][ni][1], v2=acc[mi][ni][2], v3=acc[mi][ni][3];
            if(bias){ float b0=bias[col], b1=bias[col+1]; v0+=b0; v1+=b1; v2+=b0; v3+=b1; }
            if(add0){ v0+=add0[o0]; v1+=add0[o0+1]; v2+=add0[o1]; v3+=add0[o1+1]; }
            if(add1){ v0+=add1[o0]; v1+=add1[o0+1]; v2+=add1[o1]; v3+=add1[o1+1]; }
            if(outh){
                *(bf162*)(outh + o0) = __floats2bfloat162_rn(v0, v1);
                *(bf162*)(outh + o1) = __floats2bfloat162_rn(v2, v3);
            }else{
                out[o0]=v0; out[o0+1]=v1; out[o1]=v2; out[o1+1]=v3;
            }
        }
    }
}

// ---------------- qkv GEMM: q -> fp32 [T,256]; k -> softmax(head) bf16; v -> bf16 ----------------
// kv layout [t, 512]: [0:256)=softmax_k, [256:512)=v
__global__ __launch_bounds__(256,1) void gemm_qkv_kernel(
    const bf16* __restrict__ A, const bf16* __restrict__ W,
    float* __restrict__ q, bf16* __restrict__ kv, int M, int N, int K){
    GEMM_MAINLOOP(A, W, M, N, K)
    if(bn < 256){
        // q region: plain fp32 store
        #pragma unroll
        for(int mi=0;mi<4;mi++){
            int row0 = bm + wm*64 + mi*16 + g;
            #pragma unroll
            for(int ni=0;ni<4;ni++){
                int col = bn + wn*32 + ni*8 + tg*2;
                size_t o0 = (size_t)row0*256 + col;
                size_t o1 = (size_t)(row0+8)*256 + col;
                q[o0]=acc[mi][ni][0]; q[o0+1]=acc[mi][ni][1];
                q[o1]=acc[mi][ni][2]; q[o1+1]=acc[mi][ni][3];
            }
        }
    } else if(bn < 512){
        // k region: softmax over the 32-col head (warp tile == head), bf16 store
        #pragma unroll
        for(int mi=0;mi<4;mi++){
            float m0=-1e30f, m1=-1e30f;
            #pragma unroll
            for(int ni=0;ni<4;ni++){
                m0 = fmaxf(m0, fmaxf(acc[mi][ni][0], acc[mi][ni][1]));
                m1 = fmaxf(m1, fmaxf(acc[mi][ni][2], acc[mi][ni][3]));
            }
            m0 = fmaxf(m0, __shfl_xor_sync(0xffffffffu, m0, 1));
            m0 = fmaxf(m0, __shfl_xor_sync(0xffffffffu, m0, 2));
            m1 = fmaxf(m1, __shfl_xor_sync(0xffffffffu, m1, 1));
            m1 = fmaxf(m1, __shfl_xor_sync(0xffffffffu, m1, 2));
            float s0=0.f, s1=0.f;
            #pragma unroll
            for(int ni=0;ni<4;ni++){
                acc[mi][ni][0]=expf(acc[mi][ni][0]-m0); s0+=acc[mi][ni][0];
                acc[mi][ni][1]=expf(acc[mi][ni][1]-m0); s0+=acc[mi][ni][1];
                acc[mi][ni][2]=expf(acc[mi][ni][2]-m1); s1+=acc[mi][ni][2];
                acc[mi][ni][3]=expf(acc[mi][ni][3]-m1); s1+=acc[mi][ni][3];
            }
            s0 += __shfl_xor_sync(0xffffffffu, s0, 1);
            s0 += __shfl_xor_sync(0xffffffffu, s0, 2);
            s1 += __shfl_xor_sync(0xffffffffu, s1, 1);
            s1 += __shfl_xor_sync(0xffffffffu, s1, 2);
            float i0=1.f/s0, i1=1.f/s1;
            int row0 = bm + wm*64 + mi*16 + g;
            #pragma unroll
            for(int ni=0;ni<4;ni++){
                int kcol = (bn-256) + wn*32 + ni*8 + tg*2;
                *(bf162*)(kv + (size_t)row0*512 + kcol)
                    = __floats2bfloat162_rn(acc[mi][ni][0]*i0, acc[mi][ni][1]*i0);
                *(bf162*)(kv + (size_t)(row0+8)*512 + kcol)
                    = __floats2bfloat162_rn(acc[mi][ni][2]*i1, acc[mi][ni][3]*i1);
            }
        }
    } else {
        // v region: bf16 store at kv cols [256:512)
        #pragma unroll
        for(int mi=0;mi<4;mi++){
            int row0 = bm + wm*64 + mi*16 + g;
            #pragma unroll
            for(int ni=0;ni<4;ni++){
                int vcol = (bn-512) + 256 + wn*32 + ni*8 + tg*2;
                *(bf162*)(kv + (size_t)row0*512 + vcol)
                    = __floats2bfloat162_rn(acc[mi][ni][0], acc[mi][ni][1]);
                *(bf162*)(kv + (size_t)(row0+8)*512 + vcol)
                    = __floats2bfloat162_rn(acc[mi][ni][2], acc[mi][ni][3]);
            }
        }
    }
}

// ---------------- q stats: coalesced online max/sumexp over tokens ----------------
__global__ void qstats_part(const float* __restrict__ q,
                            float* __restrict__ pm, float* __restrict__ ps){
    int b = blockIdx.x>>4, ch = blockIdx.x&15;
    int col = threadIdx.x;
    size_t base = ((size_t)b*NTOK + ch*256)*C_ + col;
    float m=-1e30f, s=0.f;
    for(int i=0;i<256;i++){
        float v = q[base + (size_t)i*C_];
        if(v>m){ s = s*expf(m-v) + 1.f; m=v; }
        else s += expf(v-m);
    }
    pm[(b*16+ch)*C_+col]=m;
    ps[(b*16+ch)*C_+col]=s;
}
__global__ void qstats_comb(const float* __restrict__ pm, const float* __restrict__ ps,
                            float* __restrict__ qmx, float* __restrict__ qrs){
    int b=blockIdx.x, col=threadIdx.x;
    float M=-1e30f;
    #pragma unroll
    for(int j=0;j<16;j++) M = fmaxf(M, pm[(b*16+j)*C_+col]);
    float S=0.f;
    #pragma unroll
    for(int j=0;j<16;j++) S += ps[(b*16+j)*C_+col]*expf(pm[(b*16+j)*C_+col]-M);
    qmx[b*C_+col]=M; qrs[b*C_+col]=1.f/S;
}

// ---------------- ctx[b,h,d,e] = sum_n k[n,d]*v[n,e] (bf16 kv) ----------------
__global__ __launch_bounds__(256) void ctx_kernel(const bf16* __restrict__ kv, float* __restrict__ ctx){
    int b = blockIdx.x>>3, h = blockIdx.x&7;
    __shared__ float ks[32][33], vs[32][33];
    int tid = threadIdx.x;
    int row = tid>>3, colq = (tid&7)*4;
    int j = tid&31, i0 = (tid>>5)*4;
    float acc[4]={0,0,0,0};
    for(int n0=0;n0<NTOK;n0+=32){
        size_t rbase = ((size_t)b*NTOK + n0 + row)*512;
        uint2 kraw = *(const uint2*)(kv + rbase + h*32 + colq);
        uint2 vraw = *(const uint2*)(kv + rbase + 256 + h*32 + colq);
        bf162 k01 = *(bf162*)&kraw.x, k23 = *(bf162*)&kraw.y;
        bf162 v01 = *(bf162*)&vraw.x, v23 = *(bf162*)&vraw.y;
        ks[row][colq+0]=__bfloat162float(k01.x); ks[row][colq+1]=__bfloat162float(k01.y);
        ks[row][colq+2]=__bfloat162float(k23.x); ks[row][colq+3]=__bfloat162float(k23.y);
        vs[row][colq+0]=__bfloat162float(v01.x); vs[row][colq+1]=__bfloat162float(v01.y);
        vs[row][colq+2]=__bfloat162float(v23.x); vs[row][colq+3]=__bfloat162float(v23.y);
        __syncthreads();
        #pragma unroll 8
        for(int nn=0;nn<32;nn++){
            float vj = vs[nn][j];
            acc[0] = fmaf(ks[nn][i0+0], vj, acc[0]);
            acc[1] = fmaf(ks[nn][i0+1], vj, acc[1]);
            acc[2] = fmaf(ks[nn][i0+2], vj, acc[2]);
            acc[3] = fmaf(ks[nn][i0+3], vj, acc[3]);
        }
        __syncthreads();
    }
    float* cb = ctx + (size_t)(b*8+h)*1024;
    #pragma unroll
    for(int r=0;r<4;r++) cb[(i0+r)*32 + j] = acc[r];
}

// ---------------- fused q-softmax + attn (bf16 out) ----------------
__global__ __launch_bounds__(256) void attn_kernel2(const float* __restrict__ q,
                                                    const float* __restrict__ ctx,
                                                    const float* __restrict__ qmx,
                                                    const float* __restrict__ qrs,
                                                    bf16* __restrict__ out){
    __shared__ float cs[8192];
    __shared__ float qs[8][256];
    int b = blockIdx.x>>6;
    int grp = blockIdx.x&63;
    int tid = threadIdx.x;
    #pragma unroll
    for(int i=0;i<32;i++) cs[tid + i*256] = ctx[(size_t)b*8192 + tid + i*256];
    float cmx = qmx[b*C_+tid];
    float crs = qrs[b*C_+tid];
    int h = tid>>5, dd = tid&31;
    const float* ch = cs + h*1024;
    __syncthreads();
    for(int t8=0;t8<8;t8++){
        size_t t0 = (size_t)b*NTOK + grp*64 + t8*8;
        #pragma unroll
        for(int i=0;i<8;i++)
            qs[i][tid] = expf(q[(t0+i)*C_ + tid] - cmx)*crs;
        __syncthreads();
        #pragma unroll
        for(int i=0;i<8;i++){
            float s = 0.f;
            #pragma unroll
            for(int e=0;e<32;e++) s = fmaf(qs[i][h*32+e], ch[e*32+dd], s);
            out[(t0+i)*256 + tid] = __float2bfloat16(s);
        }
        __syncthreads();
    }
}

// ---------------- CSDA ----------------
__global__ void ca_stats1(const float* __restrict__ x, float* __restrict__ pavg, float* __restrict__ pmax){
    int b = blockIdx.x>>5, ch = blockIdx.x&31;
    int c = threadIdx.x;
    float s=0.f, m=-1e30f;
    for(int i=0;i<128;i++){
        float v = x[((size_t)b*NTOK + ch*128+i)*C_ + c];
        s += v; m = fmaxf(m,v);
    }
    pavg[(b*32+ch)*C_+c]=s; pmax[(b*32+ch)*C_+c]=m;
}
__global__ void ca_stats2(const float* __restrict__ pavg, const float* __restrict__ pmax,
                          float* __restrict__ avg, float* __restrict__ mx){
    int b=blockIdx.x; int c=threadIdx.x;
    float s=0.f, m=-1e30f;
    for(int i=0;i<32;i++){ s+=pavg[(b*32+i)*C_+c]; m=fmaxf(m,pmax[(b*32+i)*C_+c]); }
    avg[b*C_+c]=s*(1.f/4096.f); mx[b*C_+c]=m;
}
__global__ void ca_mlp_kernel(const float* __restrict__ avg, const float* __restrict__ mx,
                              const float* __restrict__ w1, const float* __restrict__ w2,
                              float* __restrict__ ca){
    int b = blockIdx.x;
    __shared__ float ha[16], hm[16];
    int tid = threadIdx.x;
    if(tid<16){
        float sa_=0.f, sm_=0.f;
        const float* w1r = w1 + tid*C_;
        for(int c=0;c<C_;c++){ sa_ += avg[b*C_+c]*w1r[c]; sm_ += mx[b*C_+c]*w1r[c]; }
        ha[tid]=fmaxf(sa_,0.f); hm[tid]=fmaxf(sm_,0.f);
    }
    __syncthreads();
    float s=0.f;
    const float* w2r = w2 + tid*16;
    #pragma unroll
    for(int j=0;j<16;j++) s += (ha[j]+hm[j])*w2r[j];
    ca[b*C_+tid] = sigmoid_f(s);
}
__global__ void smap_kernel(const float* __restrict__ x2, const float* __restrict__ ca,
                            float* __restrict__ smean, float* __restrict__ smax){
    int w = threadIdx.x>>5, lane = threadIdx.x&31;
    int t = blockIdx.x*8 + w;
    int b = t>>12;
    const float* row = x2 + (size_t)t*C_;
    const float* cab = ca + b*C_;
    float s=0.f, m=-1e30f;
    #pragma unroll
    for(int i=0;i<8;i++){ int c=lane+32*i; float v=row[c]*cab[c]; s+=v; m=fmaxf(m,v); }
    #pragma unroll
    for(int o=16;o>0;o>>=1){ s+=__shfl_xor_sync(0xffffffffu,s,o); m=fmaxf(m,__shfl_xor_sync(0xffffffffu,m,o)); }
    if(lane==0){ smean[t]=s*(1.f/C_); smax[t]=m; }
}
__global__ void spconv_kernel(const float* __restrict__ smean, const float* __restrict__ smax,
                              const float* __restrict__ w, const float* __restrict__ bias,
                              float* __restrict__ sa){
    int t = blockIdx.x*256 + threadIdx.x;
    int b = t>>12, n = t&4095;
    int y = n>>6, x = n&63;
    float s = bias[0];
    for(int dy=-3;dy<=3;dy++){
        int yy=y+dy; if(yy<0||yy>=64) continue;
        for(int dx=-3;dx<=3;dx++){
            int xx=x+dx; if(xx<0||xx>=64) continue;
            int nn = b*4096 + yy*64+xx;
            int wi = (dy+3)*7+(dx+3);
            s += smean[nn]*w[wi] + smax[nn]*w[49+wi];
        }
    }
    sa[t] = sigmoid_f(s);
}
__global__ void final_kernel(const float* __restrict__ x2, const float* __restrict__ ca,
                             const float* __restrict__ sa, float* __restrict__ out){
    size_t i = (size_t)blockIdx.x*256 + threadIdx.x;
    int c = (int)(i & 255);
    int t = (int)(i >> 8);
    int b = t >> 12;
    out[i] = x2[i]*ca[b*256+c]*sa[t];
}

// ---------------- host ----------------
static inline void gemm(const bf16*A,const bf16*W,const float*bias,const float*a0,
                        const float*a1,float*out,bf16*outh,int M,int N,int K){
    dim3 g(N/128, M/128);
    gemm_bf16_kernel<<<g,256>>>(A,W,bias,a0,a1,out,outh,M,N,K);
}

extern "C" void kernel_launch(void* const* d_in, const int* in_sizes, int n_in,
                              void* d_out, int out_size){
    const float* x      = (const float*)d_in[0];
    const float* n1_g   = (const float*)d_in[3];
    const float* n1_b   = (const float*)d_in[4];
    const float* sr_w   = (const float*)d_in[5];
    const float* sr_b   = (const float*)d_in[6];
    const float* an_g   = (const float*)d_in[7];
    const float* an_b   = (const float*)d_in[8];
    const float* qkv_w  = (const float*)d_in[9];
    const float* proj_w = (const float*)d_in[10];
    const float* proj_b = (const float*)d_in[11];
    const float* n2_g   = (const float*)d_in[12];
    const float* n2_b   = (const float*)d_in[13];
    const float* fc1_w  = (const float*)d_in[14];
    const float* fc1_b  = (const float*)d_in[15];
    const float* dw_w   = (const float*)d_in[16];
    const float* dw_b   = (const float*)d_in[17];
    const float* fc2_w  = (const float*)d_in[18];
    const float* fc2_b  = (const float*)d_in[19];
    const float* ca_w1  = (const float*)d_in[20];
    const float* ca_w2  = (const float*)d_in[21];
    const float* sp_w   = (const float*)d_in[22];
    const float* sp_b   = (const float*)d_in[23];
    float* out = (float*)d_out;

    float *xn,*tmp,*qf,*ctx,*x1,*x2,*qmx,*qrs,*pavg,*pmax,*avg,*mx,*ca,*sme,*smx,*sa;
    bf16 *xa_h,*kv_h,*at_h,*ln2_h,*f1_h,*f2_h,*wq_h,*wp_h,*w1_h,*w2_h;
    cudaGetSymbolAddress((void**)&xn,  g_xn);
    cudaGetSymbolAddress((void**)&tmp, g_tmp);
    cudaGetSymbolAddress((void**)&qf,  g_q);
    cudaGetSymbolAddress((void**)&ctx, g_ctx);
    cudaGetSymbolAddress((void**)&x1,  g_x1);
    cudaGetSymbolAddress((void**)&x2,  g_x2);
    cudaGetSymbolAddress((void**)&qmx, g_qmx);
    cudaGetSymbolAddress((void**)&qrs, g_qrs);
    cudaGetSymbolAddress((void**)&pavg,g_pavg);
    cudaGetSymbolAddress((void**)&pmax,g_pmax);
    cudaGetSymbolAddress((void**)&avg, g_avg);
    cudaGetSymbolAddress((void**)&mx,  g_mx);
    cudaGetSymbolAddress((void**)&ca,  g_ca);
    cudaGetSymbolAddress((void**)&sme, g_sme);
    cudaGetSymbolAddress((void**)&smx, g_smx);
    cudaGetSymbolAddress((void**)&sa,  g_sa);
    cudaGetSymbolAddress((void**)&xa_h, g_xa_h);
    cudaGetSymbolAddress((void**)&kv_h, g_kv_h);
    cudaGetSymbolAddress((void**)&at_h, g_at_h);
    cudaGetSymbolAddress((void**)&ln2_h,g_ln2_h);
    cudaGetSymbolAddress((void**)&f1_h, g_f1_h);
    cudaGetSymbolAddress((void**)&f2_h, g_f2_h);
    cudaGetSymbolAddress((void**)&wq_h, g_wq_h);
    cudaGetSymbolAddress((void**)&wp_h, g_wp_h);
    cudaGetSymbolAddress((void**)&w1_h, g_w1_h);
    cudaGetSymbolAddress((void**)&w2_h, g_w2_h);

    const int TB = T_/8;

    // ---- weight conversion (tiny) ----
    cvt_kernel<<<(3*C_*C_)/256,256>>>(qkv_w,  wq_h, 3*C_*C_);
    cvt_kernel<<<(C_*C_)/256,256>>>  (proj_w, wp_h, C_*C_);
    cvt_kernel<<<(HID*C_)/256,256>>> (fc1_w,  w1_h, HID*C_);
    cvt_kernel<<<(C_*HID)/256,256>>> (fc2_w,  w2_h, C_*HID);

    // ---- attention branch ----
    ln_kernel<<<TB,256>>>(x, n1_g, n1_b, xn);
    dwconv3_kernel4<<<(T_*(C_/4))/256,256>>>(xn, sr_w, sr_b, tmp);
    adapter_kernel<<<TB,256>>>(tmp, xn, an_g, an_b, xa_h);
    {
        dim3 gq(6, T_/128);
        gemm_qkv_kernel<<<gq,256>>>(xa_h, wq_h, qf, kv_h, T_, 768, C_);
    }
    qstats_part<<<B_*16,256>>>(qf, pavg, pmax);
    qstats_comb<<<B_,256>>>(pavg, pmax, qmx, qrs);
    ctx_kernel<<<B_*HDS,256>>>(kv_h, ctx);
    attn_kernel2<<<B_*64,256>>>(qf, ctx, qmx, qrs, at_h);
    gemm(at_h, wp_h, proj_b, x, xn, x1, nullptr, T_, C_, C_);

    // ---- MixFFN ----
    ln_bf16_kernel<<<TB,256>>>(x1, n2_g, n2_b, ln2_h);
    gemm(ln2_h, w1_h, fc1_b, nullptr, nullptr, nullptr, f1_h, T_, HID, C_);
    dwconv3_h_kernel<<<(T_*(HID/4))/256,256>>>(f1_h, dw_w, dw_b, f2_h);
    gemm(f2_h, w2_h, fc2_b, x1, nullptr, x2, nullptr, T_, C_, HID);

    // ---- CSDA ----
    ca_stats1<<<B_*32,256>>>(x2, pavg, pmax);
    ca_stats2<<<B_,256>>>(pavg, pmax, avg, mx);
    ca_mlp_kernel<<<B_,256>>>(avg, mx, ca_w1, ca_w2, ca);
    smap_kernel<<<TB,256>>>(x2, ca, sme, smx);
    spconv_kernel<<<T_/256,256>>>(sme, smx, sp_w, sp_b, sa);
    final_kernel<<<(T_*C_)/256,256>>>(x2, ca, sa, out);
}